// round 4
// baseline (speedup 1.0000x reference)
#include <cuda_runtime.h>
#include <math.h>

#define BB 4
#define DD 49
#define CC 512
#define C2 256
#define NN_ 27
#define NE 729      // N*N
#define ND 1323     // N*D
#define BD 196      // B*D
#define MR 5292     // B*N*D
#define BN_EPS 1e-5f
#define SCALE 0.0625f   // 256^-0.5

// ~26.3M floats of scratch (static device allocation, allowed)
__device__ float g_scratch[26500000];

__constant__ int c_subidx[14] = {0,0,1,1,2,2,4,4,7,7,8,8,11,11};

// ---------------- utilities ----------------
__device__ __forceinline__ float blockReduceSum(float v, float* sh) {
    __syncthreads();
    int lane = threadIdx.x & 31, w = threadIdx.x >> 5;
#pragma unroll
    for (int o = 16; o; o >>= 1) v += __shfl_xor_sync(0xffffffffu, v, o);
    if (lane == 0) sh[w] = v;
    __syncthreads();
    float r = 0.f;
    if (w == 0) {
        int nw = (blockDim.x + 31) >> 5;
        r = (lane < nw) ? sh[lane] : 0.f;
#pragma unroll
        for (int o = 16; o; o >>= 1) r += __shfl_xor_sync(0xffffffffu, r, o);
    }
    return r;
}

// ---------------- generic tiled GEMM: C = alpha * A @ op(B) + bias ----------------
// TRANSB=true : B is [N,K] row-major (torch Linear weight), C += A@B^T
// TRANSB=false: B is [K,N] row-major, C += A@B
template<bool TRANSB>
__global__ void gemm_kernel(const float* __restrict__ A, size_t sA,
                            const float* __restrict__ Bm, size_t sB,
                            float* __restrict__ Cm, size_t sC,
                            const float* __restrict__ bias, size_t sBias,
                            int M, int Nn, int K, float alpha)
{
    const int BM = 64, BN = 64, BK = 16;
    int bz = blockIdx.z;
    A  += (size_t)bz * sA;
    Bm += (size_t)bz * sB;
    Cm += (size_t)bz * sC;
    int m0 = blockIdx.y * BM, n0 = blockIdx.x * BN;

    __shared__ float As[BK][BM + 1];
    __shared__ float Bs[BK][BN + 1];

    int tid = threadIdx.x;
    int ty = tid >> 4, tx = tid & 15;
    float acc[4][4] = {};

    for (int k0 = 0; k0 < K; k0 += BK) {
#pragma unroll
        for (int t = 0; t < 4; t++) {
            int e = tid + t * 256;
            int m = e >> 4, k = e & 15;
            float v = 0.f;
            int gm = m0 + m, gk = k0 + k;
            if (gm < M && gk < K) v = A[(size_t)gm * K + gk];
            As[k][m] = v;
        }
#pragma unroll
        for (int t = 0; t < 4; t++) {
            int e = tid + t * 256;
            float v = 0.f;
            if (TRANSB) {
                int n = e >> 4, k = e & 15;
                int gn = n0 + n, gk = k0 + k;
                if (gn < Nn && gk < K) v = Bm[(size_t)gn * K + gk];
                Bs[k][n] = v;
            } else {
                int k = e >> 6, n = e & 63;
                int gk = k0 + k, gn = n0 + n;
                if (gk < K && gn < Nn) v = Bm[(size_t)gk * Nn + gn];
                Bs[k][n] = v;
            }
        }
        __syncthreads();
#pragma unroll
        for (int kk = 0; kk < BK; kk++) {
            float a[4], b[4];
#pragma unroll
            for (int i = 0; i < 4; i++) a[i] = As[kk][ty * 4 + i];
#pragma unroll
            for (int j = 0; j < 4; j++) b[j] = Bs[kk][tx * 4 + j];
#pragma unroll
            for (int i = 0; i < 4; i++)
#pragma unroll
                for (int j = 0; j < 4; j++)
                    acc[i][j] += a[i] * b[j];
        }
        __syncthreads();
    }

    const float* bp = bias ? (bias + (size_t)bz * sBias) : nullptr;
#pragma unroll
    for (int i = 0; i < 4; i++) {
        int gm = m0 + ty * 4 + i;
        if (gm >= M) continue;
#pragma unroll
        for (int j = 0; j < 4; j++) {
            int gn = n0 + tx * 4 + j;
            if (gn >= Nn) continue;
            float v = acc[i][j] * alpha;
            if (bp) v += bp[gn];
            Cm[(size_t)gm * Nn + gn] = v;
        }
    }
}

// ---------------- misc precompute: bias2 = ep_W @ arm_vb ; sums of ep_b ----------------
__global__ void misc_kernel(const float* __restrict__ epW, const float* __restrict__ armvb,
                            const float* __restrict__ epb, float* bias2, float* misc)
{
    int t = threadIdx.x;  // 512
    float s = 0.f;
    for (int c = 0; c < CC; c++) s += epW[(size_t)t * CC + c] * armvb[c];
    bias2[t] = s;
    __shared__ float red[32];
    float v = epb[t];
    float s1 = blockReduceSum(v, red);
    float s2 = blockReduceSum(v * v, red);
    if (t == 0) { misc[0] = s1; misc[1] = s2; }
}

// ---------------- node BN stats over (B,D) per (n,c), from tmp [27,196,512] ----------------
__global__ void bnstat_node_kernel(const float* __restrict__ tmp, float* mean, float* rstd)
{
    int idx = blockIdx.x * blockDim.x + threadIdx.x;
    if (idx >= NN_ * CC) return;
    int n = idx >> 9, c = idx & 511;
    const float* p = tmp + (size_t)n * BD * CC + c;
    float s = 0.f, sq = 0.f;
    for (int r = 0; r < BD; r++) { float v = p[(size_t)r * CC]; s += v; sq += v * v; }
    float m = s / (float)BD;
    mean[idx] = m;
    rstd[idx] = rsqrtf(sq / (float)BD - m * m + BN_EPS);
}

// ---------------- f_u = relu(BN(tmp)) with layout swap -> [B,N,D,C] ----------------
__global__ void node_apply_kernel(const float* __restrict__ tmp, const float* __restrict__ mean,
                                  const float* __restrict__ rstd, const float* __restrict__ w,
                                  const float* __restrict__ bb, float* __restrict__ fu)
{
    int idx = blockIdx.x * blockDim.x + threadIdx.x;
    if (idx >= BB * NN_ * DD * CC) return;
    int c = idx & 511;
    int d = (idx >> 9) % DD;
    int n = (idx / (DD * CC)) % NN_;
    int b = idx / (NN_ * DD * CC);
    float v = tmp[((size_t)n * BD + b * DD + d) * CC + c];
    int nc = (n << 9) + c;
    fu[idx] = fmaxf((v - mean[nc]) * rstd[nc] * w[nc] + bb[nc], 0.f);
}

// ---------------- f_v[b,n,c] = mean_d f_u ----------------
__global__ void fv_mean_kernel(const float* __restrict__ fu, float* __restrict__ fv)
{
    int idx = blockIdx.x * blockDim.x + threadIdx.x;
    if (idx >= BB * NN_ * CC) return;
    int c = idx & 511;
    int n = (idx >> 9) % NN_;
    int b = idx / (NN_ * CC);
    const float* p = fu + ((size_t)(b * NN_ + n) * DD) * CC + c;
    float s = 0.f;
    for (int d = 0; d < DD; d++) s += p[(size_t)d * CC];
    fv[idx] = s * (1.f / (float)DD);
}

// ---------------- softmax over rows of length 49 (FAM attention) ----------------
__global__ void softmax49_kernel(float* __restrict__ data, int rows)
{
    int row = blockIdx.x * 8 + (threadIdx.x >> 5);
    if (row >= rows) return;
    int lane = threadIdx.x & 31;
    float* p = data + (size_t)row * DD;
    float v0 = p[lane];
    float v1 = (lane + 32 < DD) ? p[lane + 32] : -3.4e38f;
    float mx = fmaxf(v0, v1);
#pragma unroll
    for (int o = 16; o; o >>= 1) mx = fmaxf(mx, __shfl_xor_sync(0xffffffffu, mx, o));
    float e0 = __expf(v0 - mx);
    float e1 = (lane + 32 < DD) ? __expf(v1 - mx) : 0.f;
    float s = e0 + e1;
#pragma unroll
    for (int o = 16; o; o >>= 1) s += __shfl_xor_sync(0xffffffffu, s, o);
    float inv = 1.f / s;
    p[lane] = e0 * inv;
    if (lane + 32 < DD) p[lane + 32] = e1 * inv;
}

// ---------------- Ms (row sums) and Mb (rows @ ep_b) of VP ----------------
__global__ void msmb_kernel(const float* __restrict__ VP, const float* __restrict__ epb,
                            float* __restrict__ Ms, float* __restrict__ Mb)
{
    int row = blockIdx.x * 8 + (threadIdx.x >> 5);
    if (row >= MR) return;
    int lane = threadIdx.x & 31;
    const float* p = VP + (size_t)row * CC;
    float s = 0.f, sb = 0.f;
    for (int c = lane; c < CC; c += 32) { float v = p[c]; s += v; sb += v * epb[c]; }
#pragma unroll
    for (int o = 16; o; o >>= 1) {
        s  += __shfl_xor_sync(0xffffffffu, s, o);
        sb += __shfl_xor_sync(0xffffffffu, sb, o);
    }
    if (lane == 0) { Ms[row] = s; Mb[row] = sb; }
}

// ---------------- per-edge kernel: softmax, BN stats partials, token-mean pre-BN ----------------
__global__ void edge_kernel(const float* __restrict__ dots, const float* __restrict__ VP,
                            const float* __restrict__ MMT, const float* __restrict__ Ms,
                            const float* __restrict__ Mb, const float* __restrict__ epb,
                            const float* __restrict__ misc,
                            float* __restrict__ part1, float* __restrict__ part2,
                            float* __restrict__ fep)
{
    int e = blockIdx.x, b = blockIdx.y;
    int i = e / NN_, j = e % NN_;
    __shared__ float A[DD][52];
    __shared__ float cs[DD];
    __shared__ float red[32];
    int tid = threadIdx.x, lane = tid & 31, w = tid >> 5;

    const float* P = dots + (size_t)b * ND * ND + (size_t)(j * DD) * ND + i * DD;
    for (int d = w; d < DD; d += 8) {
        const float* pr = P + (size_t)d * ND;
        float v0 = pr[lane];
        float v1 = (lane + 32 < DD) ? pr[lane + 32] : -3.4e38f;
        float mx = fmaxf(v0, v1);
#pragma unroll
        for (int o = 16; o; o >>= 1) mx = fmaxf(mx, __shfl_xor_sync(0xffffffffu, mx, o));
        float e0 = __expf(v0 - mx);
        float e1 = (lane + 32 < DD) ? __expf(v1 - mx) : 0.f;
        float s = e0 + e1;
#pragma unroll
        for (int o = 16; o; o >>= 1) s += __shfl_xor_sync(0xffffffffu, s, o);
        float inv = 1.f / s;
        A[d][lane] = e0 * inv;
        if (lane + 32 < DD) A[d][lane + 32] = e1 * inv;
    }
    __syncthreads();

    if (tid < DD) {
        float s = 0.f;
        for (int d = 0; d < DD; d++) s += A[d][tid];
        cs[tid] = s;
    }
    __syncthreads();

    // tr(A^T A * M M^T)
    const float* mmt = MMT + (size_t)(b * NN_ + i) * DD * DD;
    float qa = 0.f;
    for (int t = tid; t < DD * DD; t += 256) {
        int p = t / DD, q = t % DD;
        float s = 0.f;
        for (int d = 0; d < DD; d++) s += A[d][p] * A[d][q];
        qa += s * mmt[t];
    }
    int mrow = (b * NN_ + i) * DD;
    float s1l = (tid < DD) ? cs[tid] * Ms[mrow + tid] : 0.f;
    float mbl = (tid < DD) ? cs[tid] * Mb[mrow + tid] : 0.f;
    float S2q = blockReduceSum(qa, red);
    float S1  = blockReduceSum(s1l, red);
    float MBd = blockReduceSum(mbl, red);
    if (tid == 0) {
        part1[b * NE + e] = S1 + (float)DD * misc[0];
        part2[b * NE + e] = S2q + 2.f * MBd + (float)DD * misc[1];
    }

    // fep[b,e,c] = (cs/D) @ M + ep_b
    const float* vprow = VP + (size_t)(b * NN_ + i) * DD * CC;
    float* fo = fep + ((size_t)b * NE + e) * CC;
    for (int c = tid; c < CC; c += 256) {
        float acc = epb[c];
        for (int k = 0; k < DD; k++)
            acc += (cs[k] * (1.f / (float)DD)) * vprow[(size_t)k * CC + c];
        fo[c] = acc;
    }
}

// ---------------- finalize edge BN scale/shift ----------------
__global__ void edge_finalize_kernel(const float* __restrict__ p1, const float* __restrict__ p2,
                                     const float* __restrict__ w, const float* __restrict__ bb,
                                     float* sc, float* sh)
{
    int e = blockIdx.x * blockDim.x + threadIdx.x;
    if (e >= NE) return;
    float s1 = 0.f, s2 = 0.f;
    for (int b = 0; b < BB; b++) { s1 += p1[b * NE + e]; s2 += p2[b * NE + e]; }
    const float cnt = (float)(BB * DD * CC);
    float mean = s1 / cnt;
    float var = s2 / cnt - mean * mean;
    float r = rsqrtf(var + BN_EPS);
    float scale = w[e] * r;
    sc[e] = scale;
    sh[e] = bb[e] - mean * scale;
}

__global__ void fe_affine_kernel(float* __restrict__ fe, const float* __restrict__ sc,
                                 const float* __restrict__ sh)
{
    int idx = blockIdx.x * blockDim.x + threadIdx.x;
    if (idx >= BB * NE * CC) return;
    int e = (idx >> 9) % NE;
    fe[idx] = fe[idx] * sc[e] + sh[e];
}

// ---------------- GNN helpers ----------------
__global__ void m_combine_kernel(float* __restrict__ m, const float* __restrict__ vi,
                                 const float* __restrict__ vj)
{
    int idx = blockIdx.x * blockDim.x + threadIdx.x;
    if (idx >= BB * NE * CC) return;
    int c = idx & 511;
    int e = (idx >> 9) % NE;
    int b = idx / (NE * CC);
    int i = e / NN_, j = e % NN_;
    m[idx] += vi[(b * NN_ + i) * CC + c] + vj[(b * NN_ + j) * CC + c];
}

// BN stats over (B,C) per feature f; data layout [B, F, 512]
__global__ void bnstat_bc_kernel(const float* __restrict__ data, int F,
                                 const float* __restrict__ w, const float* __restrict__ bb,
                                 float* sc, float* sh)
{
    int f = blockIdx.x;
    float s = 0.f, sq = 0.f;
    for (int b = 0; b < BB; b++) {
        const float* p = data + ((size_t)b * F + f) * CC;
        for (int c = threadIdx.x; c < CC; c += blockDim.x) { float v = p[c]; s += v; sq += v * v; }
    }
    __shared__ float red[32];
    s = blockReduceSum(s, red);
    sq = blockReduceSum(sq, red);
    if (threadIdx.x == 0) {
        float mean = s / 2048.f;
        float var = sq / 2048.f - mean * mean;
        float r = rsqrtf(var + BN_EPS);
        float scale = w[f] * r;
        sc[f] = scale;
        sh[f] = bb[f] - mean * scale;
    }
}

__global__ void fe_update_kernel(float* __restrict__ fe, const float* __restrict__ m,
                                 const float* __restrict__ sc, const float* __restrict__ sh)
{
    int idx = blockIdx.x * blockDim.x + threadIdx.x;
    if (idx >= BB * NE * CC) return;
    int e = (idx >> 9) % NE;
    fe[idx] += fmaxf(m[idx] * sc[e] + sh[e], 0.f);
}

__global__ void agg_kernel(const float* __restrict__ fe, const float* __restrict__ ui,
                           const float* __restrict__ uj, float* __restrict__ agg)
{
    int idx = blockIdx.x * blockDim.x + threadIdx.x;
    if (idx >= BB * NN_ * CC) return;
    int c = idx & 511;
    int i = (idx >> 9) % NN_;
    int b = idx / (NN_ * CC);
    const float* fer = fe + ((size_t)b * NE + i * NN_) * CC + c;
    float sw = 0.f, swu = 0.f;
    for (int j = 0; j < NN_; j++) {
        float f = fer[(size_t)j * CC];
        float s = 1.f / (1.f + __expf(-f));
        float wv = __expf(s);
        sw += wv;
        swu += wv * uj[(b * NN_ + j) * CC + c];
    }
    agg[idx] = ui[idx] + swu / (sw * (float)NN_);
}

__global__ void fv_update_kernel(float* __restrict__ fv, const float* __restrict__ agg,
                                 const float* __restrict__ sc, const float* __restrict__ sh)
{
    int idx = blockIdx.x * blockDim.x + threadIdx.x;
    if (idx >= BB * NN_ * CC) return;
    int i = (idx >> 9) % NN_;
    fv[idx] += fmaxf(agg[idx] * sc[i] + sh[i], 0.f);
}

// ---------------- final SC cosine similarities ----------------
__global__ void sc_kernel(const float* __restrict__ fv, const float* __restrict__ mainsc,
                          const float* __restrict__ subsc, float* __restrict__ out)
{
    int o = blockIdx.x, b = blockIdx.y;
    int node;
    const float* anchor;
    if (o < NN_) { node = o; anchor = mainsc + (size_t)o * CC; }
    else { node = c_subidx[o - NN_]; anchor = subsc + (size_t)(o - NN_) * CC; }
    const float* fp = fv + ((size_t)b * NN_ + node) * CC;
    float dot = 0.f, nv = 0.f, na = 0.f;
    for (int c = threadIdx.x; c < CC; c += blockDim.x) {
        float f = fp[c], a = fmaxf(anchor[c], 0.f);
        dot += f * a; nv += f * f; na += a * a;
    }
    __shared__ float red[32];
    dot = blockReduceSum(dot, red);
    nv = blockReduceSum(nv, red);
    na = blockReduceSum(na, red);
    if (threadIdx.x == 0)
        out[b * 41 + o] = dot / (fmaxf(sqrtf(nv), 1e-12f) * fmaxf(sqrtf(na), 1e-12f));
}

// ==================================================================================
extern "C" void kernel_launch(void* const* d_in, const int* in_sizes, int n_in,
                              void* d_out, int out_size)
{
    const float* x       = (const float*)d_in[0];
    const float* nb_W    = (const float*)d_in[1];
    const float* nb_b    = (const float*)d_in[2];
    const float* nb_bnw  = (const float*)d_in[3];
    const float* nb_bnb  = (const float*)d_in[4];
    const float* fam_qW  = (const float*)d_in[5];
    const float* fam_qb  = (const float*)d_in[6];
    const float* fam_kW  = (const float*)d_in[7];
    const float* fam_kb  = (const float*)d_in[8];
    const float* fam_vW  = (const float*)d_in[9];
    const float* fam_vb  = (const float*)d_in[10];
    const float* arm_qW  = (const float*)d_in[11];
    const float* arm_qb  = (const float*)d_in[12];
    const float* arm_kW  = (const float*)d_in[13];
    const float* arm_kb  = (const float*)d_in[14];
    // arm_vW = d_in[15] folded into W2
    const float* arm_vb  = (const float*)d_in[16];
    const float* ep_W    = (const float*)d_in[17];
    const float* ep_b    = (const float*)d_in[18];
    const float* gem_bnw = (const float*)d_in[19];
    const float* gem_bnb = (const float*)d_in[20];
    const float* gnn_uW  = (const float*)d_in[21];
    const float* gnn_vW  = (const float*)d_in[22];
    const float* gnn_aW  = (const float*)d_in[23];
    const float* gnn_bW  = (const float*)d_in[24];
    const float* gnn_eW  = (const float*)d_in[25];
    const float* gnn_bnvw = (const float*)d_in[26];
    const float* gnn_bnvb = (const float*)d_in[27];
    const float* gnn_bnew = (const float*)d_in[28];
    const float* gnn_bneb = (const float*)d_in[29];
    const float* main_sc = (const float*)d_in[30];
    const float* sub_sc  = (const float*)d_in[31];
    const float* arm_vW  = (const float*)d_in[15];
    float* out = (float*)d_out;

    float* S = nullptr;
    cudaGetSymbolAddress((void**)&S, g_scratch);

    size_t off = 0;
    auto take = [&](size_t n) { float* p = S + off; off += n; return p; };
    float* tmp_  = take((size_t)NN_ * BD * CC);     // 2,709,504
    float* fu_   = take((size_t)BB * NN_ * DD * CC);
    float* feat_ = take((size_t)BB * ND * CC);
    float* VP_   = take((size_t)BB * ND * CC);
    float* q_    = take((size_t)BB * ND * C2);
    float* Qb_   = take((size_t)BB * ND * C2);
    float* Kb_   = take((size_t)BB * ND * C2);
    float* dots_ = take((size_t)BB * ND * ND);      // 7,001,316
    float* fe_   = take((size_t)BB * NE * CC);
    float* el_   = take((size_t)BB * NE * CC);
    float* attn_ = take((size_t)BB * ND * DD);
    float* MMT_  = take((size_t)BB * NN_ * DD * DD);
    float* kb_   = take((size_t)BB * DD * C2);
    float* vb_   = take((size_t)BB * DD * CC);
    float* fv_   = take((size_t)BB * NN_ * CC);
    float* W2_   = take((size_t)CC * CC);
    float* nmean_ = take(NN_ * CC);
    float* nrstd_ = take(NN_ * CC);
    float* Ms_   = take(MR);
    float* Mb_   = take(MR);
    float* part1_ = take(BB * NE);
    float* part2_ = take(BB * NE);
    float* esc_  = take(NE);
    float* esh_  = take(NE);
    float* vi_   = take((size_t)BB * NN_ * CC);
    float* vj_   = take((size_t)BB * NN_ * CC);
    float* ui_   = take((size_t)BB * NN_ * CC);
    float* uj_   = take((size_t)BB * NN_ * CC);
    float* agg_  = take((size_t)BB * NN_ * CC);
    float* bias2_ = take(CC);
    float* misc_ = take(2);
    float* emsc_ = take(NE);
    float* emsh_ = take(NE);
    float* nvsc_ = take(NN_);
    float* nvsh_ = take(NN_);

    auto gemm_nt = [](const float* A, size_t sA, const float* Bm, size_t sB,
                      float* Cc, size_t sC, const float* bias, size_t sBias,
                      int M, int Nn, int K, int batch, float alpha) {
        dim3 g((Nn + 63) / 64, (M + 63) / 64, batch);
        gemm_kernel<true><<<g, 256>>>(A, sA, Bm, sB, Cc, sC, bias, sBias, M, Nn, K, alpha);
    };
    auto gemm_nn = [](const float* A, size_t sA, const float* Bm, size_t sB,
                      float* Cc, size_t sC, const float* bias, size_t sBias,
                      int M, int Nn, int K, int batch, float alpha) {
        dim3 g((Nn + 63) / 64, (M + 63) / 64, batch);
        gemm_kernel<false><<<g, 256>>>(A, sA, Bm, sB, Cc, sC, bias, sBias, M, Nn, K, alpha);
    };

    // ---- precompute W2 = ep_W @ arm_vW, bias2 = ep_W @ arm_vb, ep_b sums ----
    gemm_nn(ep_W, 0, arm_vW, 0, W2_, 0, nullptr, 0, CC, CC, CC, 1, 1.f);
    misc_kernel<<<1, 512>>>(ep_W, arm_vb, ep_b, bias2_, misc_);

    // ---- node blocks: tmp[n] = x @ nb_W[n]^T + nb_b[n]; BN+relu -> f_u; GAP -> f_v ----
    gemm_nt(x, 0, nb_W, (size_t)CC * CC, tmp_, (size_t)BD * CC, nb_b, CC,
            BD, CC, CC, NN_, 1.f);
    bnstat_node_kernel<<<(NN_ * CC + 255) / 256, 256>>>(tmp_, nmean_, nrstd_);
    {
        int tot = BB * NN_ * DD * CC;
        node_apply_kernel<<<(tot + 255) / 256, 256>>>(tmp_, nmean_, nrstd_, nb_bnw, nb_bnb, fu_);
    }
    fv_mean_kernel<<<(BB * NN_ * CC + 255) / 256, 256>>>(fu_, fv_);

    // ---- FAM cross attention ----
    gemm_nt(x, 0, fam_kW, 0, kb_, 0, fam_kb, 0, BD, C2, CC, 1, 1.f);
    gemm_nt(x, 0, fam_vW, 0, vb_, 0, fam_vb, 0, BD, CC, CC, 1, 1.f);
    gemm_nt(fu_, 0, fam_qW, 0, q_, 0, fam_qb, 0, MR, C2, CC, 1, 1.f);
    gemm_nt(q_, (size_t)ND * C2, kb_, (size_t)DD * C2, attn_, (size_t)ND * DD,
            nullptr, 0, ND, DD, C2, BB, SCALE);
    softmax49_kernel<<<(MR + 7) / 8, 256>>>(attn_, MR);
    gemm_nn(attn_, (size_t)ND * DD, vb_, (size_t)DD * CC, feat_, (size_t)ND * CC,
            nullptr, 0, ND, CC, DD, BB, 1.f);

    // ---- ARM projections (V folded with ep_W into VP) ----
    gemm_nt(feat_, 0, arm_qW, 0, Qb_, 0, arm_qb, 0, MR, C2, CC, 1, 1.f);
    gemm_nt(feat_, 0, arm_kW, 0, Kb_, 0, arm_kb, 0, MR, C2, CC, 1, 1.f);
    gemm_nt(feat_, 0, W2_, 0, VP_, 0, bias2_, 0, MR, CC, CC, 1, 1.f);

    // ---- pairwise dots (all edges at once): [1323,1323] per batch ----
    gemm_nt(Qb_, (size_t)ND * C2, Kb_, (size_t)ND * C2, dots_, (size_t)ND * ND,
            nullptr, 0, ND, ND, C2, BB, SCALE);

    // ---- per-(b,i): M M^T, row sums, M@ep_b ----
    gemm_nt(VP_, (size_t)DD * CC, VP_, (size_t)DD * CC, MMT_, (size_t)DD * DD,
            nullptr, 0, DD, DD, CC, BB * NN_, 1.f);
    msmb_kernel<<<(MR + 7) / 8, 256>>>(VP_, ep_b, Ms_, Mb_);

    // ---- per-edge: softmax + BN-stat partials + token-mean pre-BN ----
    {
        dim3 g(NE, BB);
        edge_kernel<<<g, 256>>>(dots_, VP_, MMT_, Ms_, Mb_, ep_b, misc_, part1_, part2_, fe_);
    }
    edge_finalize_kernel<<<(NE + 255) / 256, 256>>>(part1_, part2_, gem_bnw, gem_bnb, esc_, esh_);
    fe_affine_kernel<<<(BB * NE * CC + 255) / 256, 256>>>(fe_, esc_, esh_);

    // ---- 2 GatedGNN layers ----
    for (int l = 0; l < 2; l++) {
        const float* aW = gnn_aW + (size_t)l * CC * CC;
        const float* bW = gnn_bW + (size_t)l * CC * CC;
        const float* uW = gnn_uW + (size_t)l * CC * CC;
        const float* vW = gnn_vW + (size_t)l * CC * CC;
        const float* eW = gnn_eW + (size_t)l * CC * CC;
        gemm_nt(fv_, 0, aW, 0, vi_, 0, nullptr, 0, BB * NN_, CC, CC, 1, 1.f);
        gemm_nt(fv_, 0, bW, 0, vj_, 0, nullptr, 0, BB * NN_, CC, CC, 1, 1.f);
        gemm_nt(fv_, 0, uW, 0, ui_, 0, nullptr, 0, BB * NN_, CC, CC, 1, 1.f);
        gemm_nt(fv_, 0, vW, 0, uj_, 0, nullptr, 0, BB * NN_, CC, CC, 1, 1.f);
        gemm_nt(fe_, 0, eW, 0, el_, 0, nullptr, 0, BB * NE, CC, CC, 1, 1.f);
        int tot = BB * NE * CC;
        m_combine_kernel<<<(tot + 255) / 256, 256>>>(el_, vi_, vj_);
        bnstat_bc_kernel<<<NE, 256>>>(el_, NE, gnn_bnew + (size_t)l * NE, gnn_bneb + (size_t)l * NE,
                                      emsc_, emsh_);
        fe_update_kernel<<<(tot + 255) / 256, 256>>>(fe_, el_, emsc_, emsh_);
        agg_kernel<<<(BB * NN_ * CC + 255) / 256, 256>>>(fe_, ui_, uj_, agg_);
        bnstat_bc_kernel<<<NN_, 256>>>(agg_, NN_, gnn_bnvw + (size_t)l * NN_,
                                       gnn_bnvb + (size_t)l * NN_, nvsc_, nvsh_);
        fv_update_kernel<<<(BB * NN_ * CC + 255) / 256, 256>>>(fv_, agg_, nvsc_, nvsh_);
    }

    // ---- SC cosine outputs ----
    {
        dim3 g(41, BB);
        sc_kernel<<<g, 128>>>(fv_, main_sc, sub_sc, out);
    }
}

// round 5
// speedup vs baseline: 1.1364x; 1.1364x over previous
#include <cuda_runtime.h>
#include <math.h>

#define BB 4
#define DD 49
#define CC 512
#define C2 256
#define NN_ 27
#define NE 729      // N*N
#define ND 1323     // N*D
#define BD 196      // B*D
#define MR 5292     // B*N*D
#define BN_EPS 1e-5f
#define SCALE 0.0625f   // 256^-0.5

__device__ float g_scratch[27000000];

__constant__ int c_subidx[14] = {0,0,1,1,2,2,4,4,7,7,8,8,11,11};

// ---------------- utilities ----------------
__device__ __forceinline__ float blockReduceSum(float v, float* sh) {
    __syncthreads();
    int lane = threadIdx.x & 31, w = threadIdx.x >> 5;
#pragma unroll
    for (int o = 16; o; o >>= 1) v += __shfl_xor_sync(0xffffffffu, v, o);
    if (lane == 0) sh[w] = v;
    __syncthreads();
    float r = 0.f;
    if (w == 0) {
        int nw = (blockDim.x + 31) >> 5;
        r = (lane < nw) ? sh[lane] : 0.f;
#pragma unroll
        for (int o = 16; o; o >>= 1) r += __shfl_xor_sync(0xffffffffu, r, o);
    }
    return r;
}

// ---------------- FAST tiled GEMM (K % 16 == 0): C = alpha * A @ op(B) + bias --------
// 128x64 tile, 256 threads, 8x4 per thread, float4 loads, register double-buffer.
// TRANSB=true : B is [N,K] row-major, C = A@B^T ; TRANSB=false: B is [K,N].
template<bool TRANSB>
__global__ void __launch_bounds__(256, 2)
gemm_fast(const float* __restrict__ A, size_t sA,
          const float* __restrict__ Bm, size_t sB,
          float* __restrict__ Cm, size_t sC,
          const float* __restrict__ bias, size_t sBias,
          int M, int Nn, int K, float alpha)
{
    const int BM = 128, BN = 64, BK = 16;
    int bz = blockIdx.z;
    A  += (size_t)bz * sA;
    Bm += (size_t)bz * sB;
    Cm += (size_t)bz * sC;
    int m0 = blockIdx.y * BM, n0 = blockIdx.x * BN;

    __shared__ float As[BK][BM];
    __shared__ float Bs[BK][BN];

    int tid = threadIdx.x;
    int tx = tid & 15, ty = tid >> 4;

    // A tile load mapping: 4 float4 per row along K, 2 rows per thread
    int ar0 = tid >> 2;          // 0..63
    int ar1 = ar0 + 64;          // 64..127
    int ak  = (tid & 3) << 2;    // 0,4,8,12
    int gm0 = m0 + ar0, gm1 = m0 + ar1;
    bool a0ok = gm0 < M, a1ok = gm1 < M;
    const float* Arow0 = A + (size_t)gm0 * K + ak;
    const float* Arow1 = A + (size_t)gm1 * K + ak;

    // B tile load mapping
    int bn = 0, bkq = 0, bk = 0, bnq = 0;
    const float* Bptr = Bm;
    bool bok = false;
    if (TRANSB) {
        bn = tid >> 2; bkq = (tid & 3) << 2;
        int gn = n0 + bn;
        bok = gn < Nn;
        Bptr = Bm + (size_t)gn * K + bkq;
    } else {
        bk = tid >> 4; bnq = (tid & 15) << 2;
        int gn = n0 + bnq;
        bok = (gn + 3) < Nn;
        Bptr = Bm + (size_t)bk * Nn + gn;
    }

    const float4 z4 = make_float4(0.f, 0.f, 0.f, 0.f);

    float acc[8][4];
#pragma unroll
    for (int i = 0; i < 8; i++)
#pragma unroll
        for (int j = 0; j < 4; j++) acc[i][j] = 0.f;

    auto loadB = [&](int k0) -> float4 {
        if (TRANSB) {
            return bok ? *(const float4*)(Bptr + k0) : z4;
        } else {
            const float* p = Bptr + (size_t)k0 * Nn;
            if (bok) return *(const float4*)p;
            float4 r = z4;
            int gn = n0 + bnq;
            if (gn < Nn)     r.x = p[0];
            if (gn + 1 < Nn) r.y = p[1];
            if (gn + 2 < Nn) r.z = p[2];
            return r;
        }
    };
    auto store = [&](float4 a0, float4 a1, float4 b) {
        As[ak + 0][ar0] = a0.x; As[ak + 1][ar0] = a0.y;
        As[ak + 2][ar0] = a0.z; As[ak + 3][ar0] = a0.w;
        As[ak + 0][ar1] = a1.x; As[ak + 1][ar1] = a1.y;
        As[ak + 2][ar1] = a1.z; As[ak + 3][ar1] = a1.w;
        if (TRANSB) {
            Bs[bkq + 0][bn] = b.x; Bs[bkq + 1][bn] = b.y;
            Bs[bkq + 2][bn] = b.z; Bs[bkq + 3][bn] = b.w;
        } else {
            *(float4*)&Bs[bk][bnq] = b;
        }
    };

    int KT = K >> 4;
    {
        float4 pa0 = a0ok ? *(const float4*)Arow0 : z4;
        float4 pa1 = a1ok ? *(const float4*)Arow1 : z4;
        float4 pb  = loadB(0);
        store(pa0, pa1, pb);
    }
    __syncthreads();

    for (int kt = 0; kt < KT; kt++) {
        float4 na0, na1, nb;
        bool more = (kt + 1) < KT;
        if (more) {
            int k0 = (kt + 1) << 4;
            na0 = a0ok ? *(const float4*)(Arow0 + k0) : z4;
            na1 = a1ok ? *(const float4*)(Arow1 + k0) : z4;
            nb  = loadB(k0);
        }
#pragma unroll
        for (int kk = 0; kk < BK; kk++) {
            float4 b4 = *(const float4*)&Bs[kk][tx << 2];
            float4 aA = *(const float4*)&As[kk][ty << 3];
            float4 aB = *(const float4*)&As[kk][(ty << 3) + 4];
            float a[8] = {aA.x, aA.y, aA.z, aA.w, aB.x, aB.y, aB.z, aB.w};
            float bv[4] = {b4.x, b4.y, b4.z, b4.w};
#pragma unroll
            for (int i = 0; i < 8; i++)
#pragma unroll
                for (int j = 0; j < 4; j++)
                    acc[i][j] += a[i] * bv[j];
        }
        __syncthreads();
        if (more) store(na0, na1, nb);
        __syncthreads();
    }

    const float* bp = bias ? (bias + (size_t)bz * sBias) : nullptr;
#pragma unroll
    for (int i = 0; i < 8; i++) {
        int gm = m0 + (ty << 3) + i;
        if (gm >= M) continue;
        float* crow = Cm + (size_t)gm * Nn;
#pragma unroll
        for (int j = 0; j < 4; j++) {
            int gn = n0 + (tx << 2) + j;
            if (gn >= Nn) continue;
            float v = acc[i][j] * alpha;
            if (bp) v += bp[gn];
            crow[gn] = v;
        }
    }
}

// ---------------- generic tiled GEMM (any K): C = alpha * A @ op(B) + bias ------------
template<bool TRANSB>
__global__ void gemm_kernel(const float* __restrict__ A, size_t sA,
                            const float* __restrict__ Bm, size_t sB,
                            float* __restrict__ Cm, size_t sC,
                            const float* __restrict__ bias, size_t sBias,
                            int M, int Nn, int K, float alpha)
{
    const int BM = 64, BN = 64, BK = 16;
    int bz = blockIdx.z;
    A  += (size_t)bz * sA;
    Bm += (size_t)bz * sB;
    Cm += (size_t)bz * sC;
    int m0 = blockIdx.y * BM, n0 = blockIdx.x * BN;

    __shared__ float As[BK][BM + 1];
    __shared__ float Bs[BK][BN + 1];

    int tid = threadIdx.x;
    int ty = tid >> 4, tx = tid & 15;
    float acc[4][4] = {};

    for (int k0 = 0; k0 < K; k0 += BK) {
#pragma unroll
        for (int t = 0; t < 4; t++) {
            int e = tid + t * 256;
            int m = e >> 4, k = e & 15;
            float v = 0.f;
            int gm = m0 + m, gk = k0 + k;
            if (gm < M && gk < K) v = A[(size_t)gm * K + gk];
            As[k][m] = v;
        }
#pragma unroll
        for (int t = 0; t < 4; t++) {
            int e = tid + t * 256;
            float v = 0.f;
            if (TRANSB) {
                int n = e >> 4, k = e & 15;
                int gn = n0 + n, gk = k0 + k;
                if (gn < Nn && gk < K) v = Bm[(size_t)gn * K + gk];
                Bs[k][n] = v;
            } else {
                int k = e >> 6, n = e & 63;
                int gk = k0 + k, gn = n0 + n;
                if (gk < K && gn < Nn) v = Bm[(size_t)gk * Nn + gn];
                Bs[k][n] = v;
            }
        }
        __syncthreads();
#pragma unroll
        for (int kk = 0; kk < BK; kk++) {
            float a[4], b[4];
#pragma unroll
            for (int i = 0; i < 4; i++) a[i] = As[kk][ty * 4 + i];
#pragma unroll
            for (int j = 0; j < 4; j++) b[j] = Bs[kk][tx * 4 + j];
#pragma unroll
            for (int i = 0; i < 4; i++)
#pragma unroll
                for (int j = 0; j < 4; j++)
                    acc[i][j] += a[i] * b[j];
        }
        __syncthreads();
    }

    const float* bp = bias ? (bias + (size_t)bz * sBias) : nullptr;
#pragma unroll
    for (int i = 0; i < 4; i++) {
        int gm = m0 + ty * 4 + i;
        if (gm >= M) continue;
#pragma unroll
        for (int j = 0; j < 4; j++) {
            int gn = n0 + tx * 4 + j;
            if (gn >= Nn) continue;
            float v = acc[i][j] * alpha;
            if (bp) v += bp[gn];
            Cm[(size_t)gm * Nn + gn] = v;
        }
    }
}

// ---------------- misc precompute: bias2 = ep_W @ arm_vb ; sums of ep_b ----------------
__global__ void misc_kernel(const float* __restrict__ epW, const float* __restrict__ armvb,
                            const float* __restrict__ epb, float* bias2, float* misc)
{
    int t = threadIdx.x;  // 512
    float s = 0.f;
    for (int c = 0; c < CC; c++) s += epW[(size_t)t * CC + c] * armvb[c];
    bias2[t] = s;
    __shared__ float red[32];
    float v = epb[t];
    float s1 = blockReduceSum(v, red);
    float s2 = blockReduceSum(v * v, red);
    if (t == 0) { misc[0] = s1; misc[1] = s2; }
}

// ---------------- node BN stats over (B,D) per (n,c) ----------------
__global__ void bnstat_node_kernel(const float* __restrict__ tmp, float* mean, float* rstd)
{
    int idx = blockIdx.x * blockDim.x + threadIdx.x;
    if (idx >= NN_ * CC) return;
    int n = idx >> 9, c = idx & 511;
    const float* p = tmp + (size_t)n * BD * CC + c;
    float s = 0.f, sq = 0.f;
    for (int r = 0; r < BD; r++) { float v = p[(size_t)r * CC]; s += v; sq += v * v; }
    float m = s / (float)BD;
    mean[idx] = m;
    rstd[idx] = rsqrtf(sq / (float)BD - m * m + BN_EPS);
}

// ---------------- f_u = relu(BN(tmp)) with layout swap -> [B,N,D,C] ----------------
__global__ void node_apply_kernel(const float* __restrict__ tmp, const float* __restrict__ mean,
                                  const float* __restrict__ rstd, const float* __restrict__ w,
                                  const float* __restrict__ bb, float* __restrict__ fu)
{
    int idx = blockIdx.x * blockDim.x + threadIdx.x;
    if (idx >= BB * NN_ * DD * CC) return;
    int c = idx & 511;
    int d = (idx >> 9) % DD;
    int n = (idx / (DD * CC)) % NN_;
    int b = idx / (NN_ * DD * CC);
    float v = tmp[((size_t)n * BD + b * DD + d) * CC + c];
    int nc = (n << 9) + c;
    fu[idx] = fmaxf((v - mean[nc]) * rstd[nc] * w[nc] + bb[nc], 0.f);
}

// ---------------- f_v[b,n,c] = mean_d f_u ----------------
__global__ void fv_mean_kernel(const float* __restrict__ fu, float* __restrict__ fv)
{
    int idx = blockIdx.x * blockDim.x + threadIdx.x;
    if (idx >= BB * NN_ * CC) return;
    int c = idx & 511;
    int n = (idx >> 9) % NN_;
    int b = idx / (NN_ * CC);
    const float* p = fu + ((size_t)(b * NN_ + n) * DD) * CC + c;
    float s = 0.f;
    for (int d = 0; d < DD; d++) s += p[(size_t)d * CC];
    fv[idx] = s * (1.f / (float)DD);
}

// ---------------- softmax over rows of length 49 (FAM attention) ----------------
__global__ void softmax49_kernel(float* __restrict__ data, int rows)
{
    int row = blockIdx.x * 8 + (threadIdx.x >> 5);
    if (row >= rows) return;
    int lane = threadIdx.x & 31;
    float* p = data + (size_t)row * DD;
    float v0 = p[lane];
    float v1 = (lane + 32 < DD) ? p[lane + 32] : -3.4e38f;
    float mx = fmaxf(v0, v1);
#pragma unroll
    for (int o = 16; o; o >>= 1) mx = fmaxf(mx, __shfl_xor_sync(0xffffffffu, mx, o));
    float e0 = __expf(v0 - mx);
    float e1 = (lane + 32 < DD) ? __expf(v1 - mx) : 0.f;
    float s = e0 + e1;
#pragma unroll
    for (int o = 16; o; o >>= 1) s += __shfl_xor_sync(0xffffffffu, s, o);
    float inv = 1.f / s;
    p[lane] = e0 * inv;
    if (lane + 32 < DD) p[lane + 32] = e1 * inv;
}

// ---------------- Ms (row sums) and Mb (rows @ ep_b) of VP ----------------
__global__ void msmb_kernel(const float* __restrict__ VP, const float* __restrict__ epb,
                            float* __restrict__ Ms, float* __restrict__ Mb)
{
    int row = blockIdx.x * 8 + (threadIdx.x >> 5);
    if (row >= MR) return;
    int lane = threadIdx.x & 31;
    const float* p = VP + (size_t)row * CC;
    float s = 0.f, sb = 0.f;
    for (int c = lane; c < CC; c += 32) { float v = p[c]; s += v; sb += v * epb[c]; }
#pragma unroll
    for (int o = 16; o; o >>= 1) {
        s  += __shfl_xor_sync(0xffffffffu, s, o);
        sb += __shfl_xor_sync(0xffffffffu, sb, o);
    }
    if (lane == 0) { Ms[row] = s; Mb[row] = sb; }
}

// ---------------- per-edge kernel: softmax + BN-stat partials + colsum export --------
__global__ void edge_kernel(const float* __restrict__ dots, const float* __restrict__ MMT,
                            const float* __restrict__ Ms, const float* __restrict__ Mb,
                            const float* __restrict__ misc,
                            float* __restrict__ part1, float* __restrict__ part2,
                            float* __restrict__ csbuf)
{
    int e = blockIdx.x, b = blockIdx.y;
    int i = e / NN_, j = e % NN_;
    __shared__ float A[DD][52];
    __shared__ float cs[DD];
    __shared__ float red[32];
    int tid = threadIdx.x, lane = tid & 31, w = tid >> 5;

    const float* P = dots + (size_t)b * ND * ND + (size_t)(j * DD) * ND + i * DD;
    for (int d = w; d < DD; d += 8) {
        const float* pr = P + (size_t)d * ND;
        float v0 = pr[lane];
        float v1 = (lane + 32 < DD) ? pr[lane + 32] : -3.4e38f;
        float mx = fmaxf(v0, v1);
#pragma unroll
        for (int o = 16; o; o >>= 1) mx = fmaxf(mx, __shfl_xor_sync(0xffffffffu, mx, o));
        float e0 = __expf(v0 - mx);
        float e1 = (lane + 32 < DD) ? __expf(v1 - mx) : 0.f;
        float s = e0 + e1;
#pragma unroll
        for (int o = 16; o; o >>= 1) s += __shfl_xor_sync(0xffffffffu, s, o);
        float inv = 1.f / s;
        A[d][lane] = e0 * inv;
        if (lane + 32 < DD) A[d][lane + 32] = e1 * inv;
    }
    __syncthreads();

    if (tid < DD) {
        float s = 0.f;
        for (int d = 0; d < DD; d++) s += A[d][tid];
        cs[tid] = s;
        csbuf[((size_t)(b * NN_ + i) * NN_ + j) * DD + tid] = s * (1.f / (float)DD);
    }
    __syncthreads();

    // tr(A^T A * M M^T)
    const float* mmt = MMT + (size_t)(b * NN_ + i) * DD * DD;
    float qa = 0.f;
    for (int t = tid; t < DD * DD; t += 256) {
        int p = t / DD, q = t % DD;
        float s = 0.f;
        for (int d = 0; d < DD; d++) s += A[d][p] * A[d][q];
        qa += s * mmt[t];
    }
    int mrow = (b * NN_ + i) * DD;
    float s1l = (tid < DD) ? cs[tid] * Ms[mrow + tid] : 0.f;
    float mbl = (tid < DD) ? cs[tid] * Mb[mrow + tid] : 0.f;
    float S2q = blockReduceSum(qa, red);
    float S1  = blockReduceSum(s1l, red);
    float MBd = blockReduceSum(mbl, red);
    if (tid == 0) {
        part1[b * NE + e] = S1 + (float)DD * misc[0];
        part2[b * NE + e] = S2q + 2.f * MBd + (float)DD * misc[1];
    }
}

// ---------------- finalize edge BN scale/shift ----------------
__global__ void edge_finalize_kernel(const float* __restrict__ p1, const float* __restrict__ p2,
                                     const float* __restrict__ w, const float* __restrict__ bb,
                                     float* sc, float* sh)
{
    int e = blockIdx.x * blockDim.x + threadIdx.x;
    if (e >= NE) return;
    float s1 = 0.f, s2 = 0.f;
    for (int b = 0; b < BB; b++) { s1 += p1[b * NE + e]; s2 += p2[b * NE + e]; }
    const float cnt = (float)(BB * DD * CC);
    float mean = s1 / cnt;
    float var = s2 / cnt - mean * mean;
    float r = rsqrtf(var + BN_EPS);
    float scale = w[e] * r;
    sc[e] = scale;
    sh[e] = bb[e] - mean * scale;
}

__global__ void fe_affine_kernel(float* __restrict__ fe, const float* __restrict__ sc,
                                 const float* __restrict__ sh)
{
    int idx = blockIdx.x * blockDim.x + threadIdx.x;
    if (idx >= BB * NE * CC) return;
    int e = (idx >> 9) % NE;
    fe[idx] = fe[idx] * sc[e] + sh[e];
}

// ---------------- GNN helpers ----------------
__global__ void m_combine_kernel(float* __restrict__ m, const float* __restrict__ vi,
                                 const float* __restrict__ vj)
{
    int idx = blockIdx.x * blockDim.x + threadIdx.x;
    if (idx >= BB * NE * CC) return;
    int c = idx & 511;
    int e = (idx >> 9) % NE;
    int b = idx / (NE * CC);
    int i = e / NN_, j = e % NN_;
    m[idx] += vi[(b * NN_ + i) * CC + c] + vj[(b * NN_ + j) * CC + c];
}

// BN stats over (B,C) per feature f; data layout [B, F, 512]
__global__ void bnstat_bc_kernel(const float* __restrict__ data, int F,
                                 const float* __restrict__ w, const float* __restrict__ bb,
                                 float* sc, float* sh)
{
    int f = blockIdx.x;
    float s = 0.f, sq = 0.f;
    for (int b = 0; b < BB; b++) {
        const float* p = data + ((size_t)b * F + f) * CC;
        for (int c = threadIdx.x; c < CC; c += blockDim.x) { float v = p[c]; s += v; sq += v * v; }
    }
    __shared__ float red[32];
    s = blockReduceSum(s, red);
    sq = blockReduceSum(sq, red);
    if (threadIdx.x == 0) {
        float mean = s / 2048.f;
        float var = sq / 2048.f - mean * mean;
        float r = rsqrtf(var + BN_EPS);
        float scale = w[f] * r;
        sc[f] = scale;
        sh[f] = bb[f] - mean * scale;
    }
}

__global__ void fe_update_kernel(float* __restrict__ fe, const float* __restrict__ m,
                                 const float* __restrict__ sc, const float* __restrict__ sh)
{
    int idx = blockIdx.x * blockDim.x + threadIdx.x;
    if (idx >= BB * NE * CC) return;
    int e = (idx >> 9) % NE;
    fe[idx] += fmaxf(m[idx] * sc[e] + sh[e], 0.f);
}

__global__ void agg_kernel(const float* __restrict__ fe, const float* __restrict__ ui,
                           const float* __restrict__ uj, float* __restrict__ agg)
{
    int idx = blockIdx.x * blockDim.x + threadIdx.x;
    if (idx >= BB * NN_ * CC) return;
    int c = idx & 511;
    int i = (idx >> 9) % NN_;
    int b = idx / (NN_ * CC);
    const float* fer = fe + ((size_t)b * NE + i * NN_) * CC + c;
    float sw = 0.f, swu = 0.f;
    for (int j = 0; j < NN_; j++) {
        float f = fer[(size_t)j * CC];
        float s = 1.f / (1.f + __expf(-f));
        float wv = __expf(s);
        sw += wv;
        swu += wv * uj[(b * NN_ + j) * CC + c];
    }
    agg[idx] = ui[idx] + swu / (sw * (float)NN_);
}

__global__ void fv_update_kernel(float* __restrict__ fv, const float* __restrict__ agg,
                                 const float* __restrict__ sc, const float* __restrict__ sh)
{
    int idx = blockIdx.x * blockDim.x + threadIdx.x;
    if (idx >= BB * NN_ * CC) return;
    int i = (idx >> 9) % NN_;
    fv[idx] += fmaxf(agg[idx] * sc[i] + sh[i], 0.f);
}

// ---------------- final SC cosine similarities ----------------
__global__ void sc_kernel(const float* __restrict__ fv, const float* __restrict__ mainsc,
                          const float* __restrict__ subsc, float* __restrict__ out)
{
    int o = blockIdx.x, b = blockIdx.y;
    int node;
    const float* anchor;
    if (o < NN_) { node = o; anchor = mainsc + (size_t)o * CC; }
    else { node = c_subidx[o - NN_]; anchor = subsc + (size_t)(o - NN_) * CC; }
    const float* fp = fv + ((size_t)b * NN_ + node) * CC;
    float dot = 0.f, nv = 0.f, na = 0.f;
    for (int c = threadIdx.x; c < CC; c += blockDim.x) {
        float f = fp[c], a = fmaxf(anchor[c], 0.f);
        dot += f * a; nv += f * f; na += a * a;
    }
    __shared__ float red[32];
    dot = blockReduceSum(dot, red);
    nv = blockReduceSum(nv, red);
    na = blockReduceSum(na, red);
    if (threadIdx.x == 0)
        out[b * 41 + o] = dot / (fmaxf(sqrtf(nv), 1e-12f) * fmaxf(sqrtf(na), 1e-12f));
}

// ==================================================================================
extern "C" void kernel_launch(void* const* d_in, const int* in_sizes, int n_in,
                              void* d_out, int out_size)
{
    const float* x       = (const float*)d_in[0];
    const float* nb_W    = (const float*)d_in[1];
    const float* nb_b    = (const float*)d_in[2];
    const float* nb_bnw  = (const float*)d_in[3];
    const float* nb_bnb  = (const float*)d_in[4];
    const float* fam_qW  = (const float*)d_in[5];
    const float* fam_qb  = (const float*)d_in[6];
    const float* fam_kW  = (const float*)d_in[7];
    const float* fam_kb  = (const float*)d_in[8];
    const float* fam_vW  = (const float*)d_in[9];
    const float* fam_vb  = (const float*)d_in[10];
    const float* arm_qW  = (const float*)d_in[11];
    const float* arm_qb  = (const float*)d_in[12];
    const float* arm_kW  = (const float*)d_in[13];
    const float* arm_kb  = (const float*)d_in[14];
    const float* arm_vW  = (const float*)d_in[15];
    const float* arm_vb  = (const float*)d_in[16];
    const float* ep_W    = (const float*)d_in[17];
    const float* ep_b    = (const float*)d_in[18];
    const float* gem_bnw = (const float*)d_in[19];
    const float* gem_bnb = (const float*)d_in[20];
    const float* gnn_uW  = (const float*)d_in[21];
    const float* gnn_vW  = (const float*)d_in[22];
    const float* gnn_aW  = (const float*)d_in[23];
    const float* gnn_bW  = (const float*)d_in[24];
    const float* gnn_eW  = (const float*)d_in[25];
    const float* gnn_bnvw = (const float*)d_in[26];
    const float* gnn_bnvb = (const float*)d_in[27];
    const float* gnn_bnew = (const float*)d_in[28];
    const float* gnn_bneb = (const float*)d_in[29];
    const float* main_sc = (const float*)d_in[30];
    const float* sub_sc  = (const float*)d_in[31];
    float* out = (float*)d_out;

    float* S = nullptr;
    cudaGetSymbolAddress((void**)&S, g_scratch);

    size_t off = 0;
    auto take = [&](size_t n) { float* p = S + off; off += (n + 3) & ~(size_t)3; return p; };
    float* tmp_  = take((size_t)NN_ * BD * CC);
    float* fu_   = take((size_t)BB * NN_ * DD * CC);
    float* feat_ = take((size_t)BB * ND * CC);
    float* VP_   = take((size_t)BB * ND * CC);
    float* q_    = take((size_t)BB * ND * C2);
    float* Qb_   = take((size_t)BB * ND * C2);
    float* Kb_   = take((size_t)BB * ND * C2);
    float* dots_ = take((size_t)BB * ND * ND);
    float* fe_   = take((size_t)BB * NE * CC);
    float* el_   = take((size_t)BB * NE * CC);
    float* attn_ = take((size_t)BB * ND * DD);
    float* MMT_  = take((size_t)BB * NN_ * DD * DD);
    float* kb_   = take((size_t)BB * DD * C2);
    float* vb_   = take((size_t)BB * DD * CC);
    float* fv_   = take((size_t)BB * NN_ * CC);
    float* W2_   = take((size_t)CC * CC);
    float* csbuf_ = take((size_t)BB * NN_ * NN_ * DD);
    float* nmean_ = take(NN_ * CC);
    float* nrstd_ = take(NN_ * CC);
    float* Ms_   = take(MR);
    float* Mb_   = take(MR);
    float* part1_ = take(BB * NE);
    float* part2_ = take(BB * NE);
    float* esc_  = take(NE);
    float* esh_  = take(NE);
    float* vi_   = take((size_t)BB * NN_ * CC);
    float* vj_   = take((size_t)BB * NN_ * CC);
    float* ui_   = take((size_t)BB * NN_ * CC);
    float* uj_   = take((size_t)BB * NN_ * CC);
    float* agg_  = take((size_t)BB * NN_ * CC);
    float* bias2_ = take(CC);
    float* misc_ = take(2);
    float* emsc_ = take(NE);
    float* emsh_ = take(NE);
    float* nvsc_ = take(NN_);
    float* nvsh_ = take(NN_);

    // fast path (K % 16 == 0)
    auto fast_nt = [](const float* A, size_t sA, const float* Bm, size_t sB,
                      float* Cc, size_t sC, const float* bias, size_t sBias,
                      int M, int Nn, int K, int batch, float alpha) {
        dim3 g((Nn + 63) / 64, (M + 127) / 128, batch);
        gemm_fast<true><<<g, 256>>>(A, sA, Bm, sB, Cc, sC, bias, sBias, M, Nn, K, alpha);
    };
    auto fast_nn = [](const float* A, size_t sA, const float* Bm, size_t sB,
                      float* Cc, size_t sC, const float* bias, size_t sBias,
                      int M, int Nn, int K, int batch, float alpha) {
        dim3 g((Nn + 63) / 64, (M + 127) / 128, batch);
        gemm_fast<false><<<g, 256>>>(A, sA, Bm, sB, Cc, sC, bias, sBias, M, Nn, K, alpha);
    };
    // generic (any K)
    auto gen_nn = [](const float* A, size_t sA, const float* Bm, size_t sB,
                     float* Cc, size_t sC, const float* bias, size_t sBias,
                     int M, int Nn, int K, int batch, float alpha) {
        dim3 g((Nn + 63) / 64, (M + 63) / 64, batch);
        gemm_kernel<false><<<g, 256>>>(A, sA, Bm, sB, Cc, sC, bias, sBias, M, Nn, K, alpha);
    };

    // ---- precompute W2 = ep_W @ arm_vW, bias2 = ep_W @ arm_vb, ep_b sums ----
    fast_nn(ep_W, 0, arm_vW, 0, W2_, 0, nullptr, 0, CC, CC, CC, 1, 1.f);
    misc_kernel<<<1, 512>>>(ep_W, arm_vb, ep_b, bias2_, misc_);

    // ---- node blocks: tmp[n] = x @ nb_W[n]^T + nb_b[n]; BN+relu -> f_u; GAP -> f_v ----
    fast_nt(x, 0, nb_W, (size_t)CC * CC, tmp_, (size_t)BD * CC, nb_b, CC,
            BD, CC, CC, NN_, 1.f);
    bnstat_node_kernel<<<(NN_ * CC + 255) / 256, 256>>>(tmp_, nmean_, nrstd_);
    {
        int tot = BB * NN_ * DD * CC;
        node_apply_kernel<<<(tot + 255) / 256, 256>>>(tmp_, nmean_, nrstd_, nb_bnw, nb_bnb, fu_);
    }
    fv_mean_kernel<<<(BB * NN_ * CC + 255) / 256, 256>>>(fu_, fv_);

    // ---- FAM cross attention ----
    fast_nt(x, 0, fam_kW, 0, kb_, 0, fam_kb, 0, BD, C2, CC, 1, 1.f);
    fast_nt(x, 0, fam_vW, 0, vb_, 0, fam_vb, 0, BD, CC, CC, 1, 1.f);
    fast_nt(fu_, 0, fam_qW, 0, q_, 0, fam_qb, 0, MR, C2, CC, 1, 1.f);
    fast_nt(q_, (size_t)ND * C2, kb_, (size_t)DD * C2, attn_, (size_t)ND * DD,
            nullptr, 0, ND, DD, C2, BB, SCALE);
    softmax49_kernel<<<(MR + 7) / 8, 256>>>(attn_, MR);
    gen_nn(attn_, (size_t)ND * DD, vb_, (size_t)DD * CC, feat_, (size_t)ND * CC,
           nullptr, 0, ND, CC, DD, BB, 1.f);

    // ---- ARM projections (V folded with ep_W into VP) ----
    fast_nt(feat_, 0, arm_qW, 0, Qb_, 0, arm_qb, 0, MR, C2, CC, 1, 1.f);
    fast_nt(feat_, 0, arm_kW, 0, Kb_, 0, arm_kb, 0, MR, C2, CC, 1, 1.f);
    fast_nt(feat_, 0, W2_, 0, VP_, 0, bias2_, 0, MR, CC, CC, 1, 1.f);

    // ---- pairwise dots (all edges at once): [1323,1323] per batch ----
    fast_nt(Qb_, (size_t)ND * C2, Kb_, (size_t)ND * C2, dots_, (size_t)ND * ND,
            nullptr, 0, ND, ND, C2, BB, SCALE);

    // ---- per-(b,i): M M^T, row sums, M@ep_b ----
    fast_nt(VP_, (size_t)DD * CC, VP_, (size_t)DD * CC, MMT_, (size_t)DD * DD,
            nullptr, 0, DD, DD, CC, BB * NN_, 1.f);
    msmb_kernel<<<(MR + 7) / 8, 256>>>(VP_, ep_b, Ms_, Mb_);

    // ---- per-edge: softmax + BN-stat partials; export colsum/D for fe GEMM ----
    {
        dim3 g(NE, BB);
        edge_kernel<<<g, 256>>>(dots_, MMT_, Ms_, Mb_, misc_, part1_, part2_, csbuf_);
    }
    // fe[b, i*27+j, :] = (cs/D) @ VP_(b,i) + ep_b   (batched over (b,i))
    gen_nn(csbuf_, (size_t)NN_ * DD, VP_, (size_t)DD * CC, fe_, (size_t)NN_ * CC,
           ep_b, 0, NN_, CC, DD, BB * NN_, 1.f);
    edge_finalize_kernel<<<(NE + 255) / 256, 256>>>(part1_, part2_, gem_bnw, gem_bnb, esc_, esh_);
    fe_affine_kernel<<<(BB * NE * CC + 255) / 256, 256>>>(fe_, esc_, esh_);

    // ---- 2 GatedGNN layers ----
    for (int l = 0; l < 2; l++) {
        const float* aW = gnn_aW + (size_t)l * CC * CC;
        const float* bW = gnn_bW + (size_t)l * CC * CC;
        const float* uW = gnn_uW + (size_t)l * CC * CC;
        const float* vW = gnn_vW + (size_t)l * CC * CC;
        const float* eW = gnn_eW + (size_t)l * CC * CC;
        fast_nt(fv_, 0, aW, 0, vi_, 0, nullptr, 0, BB * NN_, CC, CC, 1, 1.f);
        fast_nt(fv_, 0, bW, 0, vj_, 0, nullptr, 0, BB * NN_, CC, CC, 1, 1.f);
        fast_nt(fv_, 0, uW, 0, ui_, 0, nullptr, 0, BB * NN_, CC, CC, 1, 1.f);
        fast_nt(fv_, 0, vW, 0, uj_, 0, nullptr, 0, BB * NN_, CC, CC, 1, 1.f);
        fast_nt(fe_, 0, eW, 0, el_, 0, nullptr, 0, BB * NE, CC, CC, 1, 1.f);
        int tot = BB * NE * CC;
        m_combine_kernel<<<(tot + 255) / 256, 256>>>(el_, vi_, vj_);
        bnstat_bc_kernel<<<NE, 256>>>(el_, NE, gnn_bnew + (size_t)l * NE, gnn_bneb + (size_t)l * NE,
                                      emsc_, emsh_);
        fe_update_kernel<<<(tot + 255) / 256, 256>>>(fe_, el_, emsc_, emsh_);
        agg_kernel<<<(BB * NN_ * CC + 255) / 256, 256>>>(fe_, ui_, uj_, agg_);
        bnstat_bc_kernel<<<NN_, 256>>>(agg_, NN_, gnn_bnvw + (size_t)l * NN_,
                                       gnn_bnvb + (size_t)l * NN_, nvsc_, nvsh_);
        fv_update_kernel<<<(BB * NN_ * CC + 255) / 256, 256>>>(fv_, agg_, nvsc_, nvsh_);
    }

    // ---- SC cosine outputs ----
    {
        dim3 g(41, BB);
        sc_kernel<<<g, 128>>>(fv_, main_sc, sub_sc, out);
    }
}

// round 9
// speedup vs baseline: 1.3852x; 1.2190x over previous
#include <cuda_runtime.h>
#include <math.h>

#define BB 4
#define DD 49
#define CC 512
#define C2 256
#define NN_ 27
#define NE 729      // N*N
#define ND 1323     // N*D
#define BD 196      // B*D
#define MR 5292     // B*N*D
#define NPAIR 1225  // DD*(DD+1)/2
#define BN_EPS 1e-5f
#define SCALE 0.0625f   // 256^-0.5

__device__ float g_scratch[27000000];
__device__ int g_pairs[NPAIR];

__constant__ int c_subidx[14] = {0,0,1,1,2,2,4,4,7,7,8,8,11,11};

// ---------------- utilities ----------------
__device__ __forceinline__ float blockReduceSum(float v, float* sh) {
    __syncthreads();
    int lane = threadIdx.x & 31, w = threadIdx.x >> 5;
#pragma unroll
    for (int o = 16; o; o >>= 1) v += __shfl_xor_sync(0xffffffffu, v, o);
    if (lane == 0) sh[w] = v;
    __syncthreads();
    float r = 0.f;
    if (w == 0) {
        int nw = (blockDim.x + 31) >> 5;
        r = (lane < nw) ? sh[lane] : 0.f;
#pragma unroll
        for (int o = 16; o; o >>= 1) r += __shfl_xor_sync(0xffffffffu, r, o);
    }
    return r;
}

// ---------------- FAST tiled GEMM (K % 16 == 0): C = alpha * A @ op(B) + bias --------
// 128x64 tile, 256 threads, 8x4 per thread, float4 loads, register double-buffer.
// EPI==1: epilogue adds evi[(b,i),c] + evj[(b,j),c] for row gm = b*NE + i*27 + j.
template<bool TRANSB, int EPI>
__global__ void __launch_bounds__(256, 2)
gemm_fast(const float* __restrict__ A, size_t sA,
          const float* __restrict__ Bm, size_t sB,
          float* __restrict__ Cm, size_t sC,
          const float* __restrict__ bias, size_t sBias,
          int M, int Nn, int K, float alpha,
          const float* __restrict__ evi, const float* __restrict__ evj)
{
    const int BM = 128, BN = 64, BK = 16;
    int bz = blockIdx.z;
    A  += (size_t)bz * sA;
    Bm += (size_t)bz * sB;
    Cm += (size_t)bz * sC;
    int m0 = blockIdx.y * BM, n0 = blockIdx.x * BN;

    __shared__ float As[BK][BM];
    __shared__ float Bs[BK][BN];

    int tid = threadIdx.x;
    int tx = tid & 15, ty = tid >> 4;

    int ar0 = tid >> 2;
    int ar1 = ar0 + 64;
    int ak  = (tid & 3) << 2;
    int gm0 = m0 + ar0, gm1 = m0 + ar1;
    bool a0ok = gm0 < M, a1ok = gm1 < M;
    const float* Arow0 = A + (size_t)gm0 * K + ak;
    const float* Arow1 = A + (size_t)gm1 * K + ak;

    int bn = 0, bkq = 0, bk = 0, bnq = 0;
    const float* Bptr = Bm;
    bool bok = false;
    if (TRANSB) {
        bn = tid >> 2; bkq = (tid & 3) << 2;
        int gn = n0 + bn;
        bok = gn < Nn;
        Bptr = Bm + (size_t)gn * K + bkq;
    } else {
        bk = tid >> 4; bnq = (tid & 15) << 2;
        int gn = n0 + bnq;
        bok = (gn + 3) < Nn;
        Bptr = Bm + (size_t)bk * Nn + gn;
    }

    const float4 z4 = make_float4(0.f, 0.f, 0.f, 0.f);

    float acc[8][4];
#pragma unroll
    for (int i = 0; i < 8; i++)
#pragma unroll
        for (int j = 0; j < 4; j++) acc[i][j] = 0.f;

    auto loadB = [&](int k0) -> float4 {
        if (TRANSB) {
            return bok ? *(const float4*)(Bptr + k0) : z4;
        } else {
            const float* p = Bptr + (size_t)k0 * Nn;
            if (bok) return *(const float4*)p;
            float4 r = z4;
            int gn = n0 + bnq;
            if (gn < Nn)     r.x = p[0];
            if (gn + 1 < Nn) r.y = p[1];
            if (gn + 2 < Nn) r.z = p[2];
            return r;
        }
    };
    auto store = [&](float4 a0, float4 a1, float4 b) {
        As[ak + 0][ar0] = a0.x; As[ak + 1][ar0] = a0.y;
        As[ak + 2][ar0] = a0.z; As[ak + 3][ar0] = a0.w;
        As[ak + 0][ar1] = a1.x; As[ak + 1][ar1] = a1.y;
        As[ak + 2][ar1] = a1.z; As[ak + 3][ar1] = a1.w;
        if (TRANSB) {
            Bs[bkq + 0][bn] = b.x; Bs[bkq + 1][bn] = b.y;
            Bs[bkq + 2][bn] = b.z; Bs[bkq + 3][bn] = b.w;
        } else {
            *(float4*)&Bs[bk][bnq] = b;
        }
    };

    int KT = K >> 4;
    {
        float4 pa0 = a0ok ? *(const float4*)Arow0 : z4;
        float4 pa1 = a1ok ? *(const float4*)Arow1 : z4;
        float4 pb  = loadB(0);
        store(pa0, pa1, pb);
    }
    __syncthreads();

    for (int kt = 0; kt < KT; kt++) {
        float4 na0, na1, nb;
        bool more = (kt + 1) < KT;
        if (more) {
            int k0 = (kt + 1) << 4;
            na0 = a0ok ? *(const float4*)(Arow0 + k0) : z4;
            na1 = a1ok ? *(const float4*)(Arow1 + k0) : z4;
            nb  = loadB(k0);
        }
#pragma unroll
        for (int kk = 0; kk < BK; kk++) {
            float4 b4 = *(const float4*)&Bs[kk][tx << 2];
            float4 aA = *(const float4*)&As[kk][ty << 3];
            float4 aB = *(const float4*)&As[kk][(ty << 3) + 4];
            float a[8] = {aA.x, aA.y, aA.z, aA.w, aB.x, aB.y, aB.z, aB.w};
            float bv[4] = {b4.x, b4.y, b4.z, b4.w};
#pragma unroll
            for (int i = 0; i < 8; i++)
#pragma unroll
                for (int j = 0; j < 4; j++)
                    acc[i][j] += a[i] * bv[j];
        }
        __syncthreads();
        if (more) store(na0, na1, nb);
        __syncthreads();
    }

    const float* bp = bias ? (bias + (size_t)bz * sBias) : nullptr;
#pragma unroll
    for (int i = 0; i < 8; i++) {
        int gm = m0 + (ty << 3) + i;
        if (gm >= M) continue;
        float* crow = Cm + (size_t)gm * Nn;
        const float* vip = nullptr; const float* vjp = nullptr;
        if (EPI == 1) {
            int b = gm / NE; int e = gm - b * NE;
            int ii = e / NN_; int jj = e - ii * NN_;
            vip = evi + (size_t)(b * NN_ + ii) * CC;
            vjp = evj + (size_t)(b * NN_ + jj) * CC;
        }
#pragma unroll
        for (int j = 0; j < 4; j++) {
            int gn = n0 + (tx << 2) + j;
            if (gn >= Nn) continue;
            float v = acc[i][j] * alpha;
            if (bp) v += bp[gn];
            if (EPI == 1) v += vip[gn] + vjp[gn];
            crow[gn] = v;
        }
    }
}

// ---------------- SMALL tiled GEMM (any K): 32x32 tile, 256 threads, 2x2/thread ------
template<bool TRANSB>
__global__ void gemm_small(const float* __restrict__ A, size_t sA,
                           const float* __restrict__ Bm, size_t sB,
                           float* __restrict__ Cm, size_t sC,
                           const float* __restrict__ bias, size_t sBias,
                           int M, int Nn, int K, float alpha)
{
    const int BK = 16;
    int bz = blockIdx.z;
    A  += (size_t)bz * sA;
    Bm += (size_t)bz * sB;
    Cm += (size_t)bz * sC;
    int m0 = blockIdx.y * 32, n0 = blockIdx.x * 32;

    __shared__ float As[BK][33];
    __shared__ float Bs[BK][33];

    int tid = threadIdx.x;
    int ty = tid >> 4, tx = tid & 15;
    float acc[2][2] = {};

    for (int k0 = 0; k0 < K; k0 += BK) {
#pragma unroll
        for (int t = 0; t < 2; t++) {
            int e = tid + t * 256;
            int m = e >> 4, k = e & 15;
            float v = 0.f;
            int gm = m0 + m, gk = k0 + k;
            if (gm < M && gk < K) v = A[(size_t)gm * K + gk];
            As[k][m] = v;
        }
#pragma unroll
        for (int t = 0; t < 2; t++) {
            int e = tid + t * 256;
            float v = 0.f;
            if (TRANSB) {
                int n = e >> 4, k = e & 15;
                int gn = n0 + n, gk = k0 + k;
                if (gn < Nn && gk < K) v = Bm[(size_t)gn * K + gk];
                Bs[k][n] = v;
            } else {
                int k = e >> 5, n = e & 31;
                int gk = k0 + k, gn = n0 + n;
                if (gk < K && gn < Nn) v = Bm[(size_t)gk * Nn + gn];
                Bs[k][n] = v;
            }
        }
        __syncthreads();
#pragma unroll
        for (int kk = 0; kk < BK; kk++) {
            float a0 = As[kk][2 * ty], a1 = As[kk][2 * ty + 1];
            float b0 = Bs[kk][2 * tx], b1 = Bs[kk][2 * tx + 1];
            acc[0][0] += a0 * b0; acc[0][1] += a0 * b1;
            acc[1][0] += a1 * b0; acc[1][1] += a1 * b1;
        }
        __syncthreads();
    }

    const float* bp = bias ? (bias + (size_t)bz * sBias) : nullptr;
#pragma unroll
    for (int i = 0; i < 2; i++) {
        int gm = m0 + 2 * ty + i;
        if (gm >= M) continue;
#pragma unroll
        for (int j = 0; j < 2; j++) {
            int gn = n0 + 2 * tx + j;
            if (gn >= Nn) continue;
            float v = acc[i][j] * alpha;
            if (bp) v += bp[gn];
            Cm[(size_t)gm * Nn + gn] = v;
        }
    }
}

// ---------------- pair table for symmetric trace ----------------
__global__ void pair_init_kernel(int* pairs)
{
    int t = blockIdx.x * blockDim.x + threadIdx.x;
    if (t >= NPAIR) return;
    int p = 0, base = 0;
    while (base + (DD - p) <= t) { base += DD - p; p++; }
    int q = p + (t - base);
    pairs[t] = (p << 8) | q;
}

// ---------------- misc precompute ----------------
__global__ void misc_kernel(const float* __restrict__ epW, const float* __restrict__ armvb,
                            const float* __restrict__ epb, float* bias2, float* misc)
{
    int t = threadIdx.x;  // 512
    float s = 0.f;
    for (int c = 0; c < CC; c++) s += epW[(size_t)t * CC + c] * armvb[c];
    bias2[t] = s;
    __shared__ float red[32];
    float v = epb[t];
    float s1 = blockReduceSum(v, red);
    float s2 = blockReduceSum(v * v, red);
    if (t == 0) { misc[0] = s1; misc[1] = s2; }
}

// ---------------- node BN stats over (B,D) per (n,c) ----------------
__global__ void bnstat_node_kernel(const float* __restrict__ tmp, float* mean, float* rstd)
{
    int idx = blockIdx.x * blockDim.x + threadIdx.x;
    if (idx >= NN_ * CC) return;
    int n = idx >> 9, c = idx & 511;
    const float* p = tmp + (size_t)n * BD * CC + c;
    float s = 0.f, sq = 0.f;
    for (int r = 0; r < BD; r++) { float v = p[(size_t)r * CC]; s += v; sq += v * v; }
    float m = s / (float)BD;
    mean[idx] = m;
    rstd[idx] = rsqrtf(sq / (float)BD - m * m + BN_EPS);
}

// ---------------- fused: f_u = relu(BN(tmp)) + GAP -> f_v ----------------
__global__ void node_apply_fused(const float* __restrict__ tmp, const float* __restrict__ mean,
                                 const float* __restrict__ rstd, const float* __restrict__ w,
                                 const float* __restrict__ bb,
                                 float* __restrict__ fu, float* __restrict__ fv)
{
    int idx = blockIdx.x * blockDim.x + threadIdx.x;
    if (idx >= BB * NN_ * CC) return;
    int c = idx & 511;
    int n = (idx >> 9) % NN_;
    int b = idx / (NN_ * CC);
    int nc = (n << 9) + c;
    float mu = mean[nc], rs = rstd[nc] * w[nc], bias = bb[nc];
    const float* tp = tmp + ((size_t)n * BD + b * DD) * CC + c;
    float* fp = fu + ((size_t)(b * NN_ + n) * DD) * CC + c;
    float s = 0.f;
    for (int d = 0; d < DD; d++) {
        float v = fmaxf((tp[(size_t)d * CC] - mu) * rs + bias, 0.f);
        fp[(size_t)d * CC] = v;
        s += v;
    }
    fv[idx] = s * (1.f / (float)DD);
}

// ---------------- softmax over rows of length 49 ----------------
__global__ void softmax49_kernel(float* __restrict__ data, int rows)
{
    int row = blockIdx.x * 8 + (threadIdx.x >> 5);
    if (row >= rows) return;
    int lane = threadIdx.x & 31;
    float* p = data + (size_t)row * DD;
    float v0 = p[lane];
    float v1 = (lane + 32 < DD) ? p[lane + 32] : -3.4e38f;
    float mx = fmaxf(v0, v1);
#pragma unroll
    for (int o = 16; o; o >>= 1) mx = fmaxf(mx, __shfl_xor_sync(0xffffffffu, mx, o));
    float e0 = __expf(v0 - mx);
    float e1 = (lane + 32 < DD) ? __expf(v1 - mx) : 0.f;
    float s = e0 + e1;
#pragma unroll
    for (int o = 16; o; o >>= 1) s += __shfl_xor_sync(0xffffffffu, s, o);
    float inv = 1.f / s;
    p[lane] = e0 * inv;
    if (lane + 32 < DD) p[lane + 32] = e1 * inv;
}

// ---------------- Ms (row sums) and Mb (rows @ ep_b) of VP ----------------
__global__ void msmb_kernel(const float* __restrict__ VP, const float* __restrict__ epb,
                            float* __restrict__ Ms, float* __restrict__ Mb)
{
    int row = blockIdx.x * 8 + (threadIdx.x >> 5);
    if (row >= MR) return;
    int lane = threadIdx.x & 31;
    const float* p = VP + (size_t)row * CC;
    float s = 0.f, sb = 0.f;
    for (int c = lane; c < CC; c += 32) { float v = p[c]; s += v; sb += v * epb[c]; }
#pragma unroll
    for (int o = 16; o; o >>= 1) {
        s  += __shfl_xor_sync(0xffffffffu, s, o);
        sb += __shfl_xor_sync(0xffffffffu, sb, o);
    }
    if (lane == 0) { Ms[row] = s; Mb[row] = sb; }
}

// ---------------- per-edge kernel: softmax + BN-stat partials + colsum export --------
__global__ void edge_kernel(const float* __restrict__ dots, const float* __restrict__ MMT,
                            const float* __restrict__ Ms, const float* __restrict__ Mb,
                            const float* __restrict__ misc, const int* __restrict__ pairs,
                            float* __restrict__ part1, float* __restrict__ part2,
                            float* __restrict__ csbuf)
{
    int e = blockIdx.x, b = blockIdx.y;
    int i = e / NN_, j = e % NN_;
    __shared__ float A[DD][52];
    __shared__ float cs[DD];
    __shared__ float red[32];
    int tid = threadIdx.x, lane = tid & 31, w = tid >> 5;

    const float* P = dots + (size_t)b * ND * ND + (size_t)(j * DD) * ND + i * DD;
    for (int d = w; d < DD; d += 8) {
        const float* pr = P + (size_t)d * ND;
        float v0 = pr[lane];
        float v1 = (lane + 32 < DD) ? pr[lane + 32] : -3.4e38f;
        float mx = fmaxf(v0, v1);
#pragma unroll
        for (int o = 16; o; o >>= 1) mx = fmaxf(mx, __shfl_xor_sync(0xffffffffu, mx, o));
        float e0 = __expf(v0 - mx);
        float e1 = (lane + 32 < DD) ? __expf(v1 - mx) : 0.f;
        float s = e0 + e1;
#pragma unroll
        for (int o = 16; o; o >>= 1) s += __shfl_xor_sync(0xffffffffu, s, o);
        float inv = 1.f / s;
        A[d][lane] = e0 * inv;
        if (lane + 32 < DD) A[d][lane + 32] = e1 * inv;
    }
    __syncthreads();

    if (tid < DD) {
        float s = 0.f;
        for (int d = 0; d < DD; d++) s += A[d][tid];
        cs[tid] = s;
        csbuf[((size_t)(b * NN_ + i) * NN_ + j) * DD + tid] = s * (1.f / (float)DD);
    }
    __syncthreads();

    // tr(A^T A * M M^T), both symmetric: upper triangle only
    const float* mmt = MMT + (size_t)(b * NN_ + i) * DD * DD;
    float qa = 0.f;
    for (int t = tid; t < NPAIR; t += 256) {
        int pq = pairs[t];
        int p = pq >> 8, q = pq & 255;
        float s = 0.f;
        for (int d = 0; d < DD; d++) s += A[d][p] * A[d][q];
        float mv = mmt[p * DD + q];
        qa += s * mv * ((p == q) ? 1.f : 2.f);
    }
    int mrow = (b * NN_ + i) * DD;
    float s1l = (tid < DD) ? cs[tid] * Ms[mrow + tid] : 0.f;
    float mbl = (tid < DD) ? cs[tid] * Mb[mrow + tid] : 0.f;
    float S2q = blockReduceSum(qa, red);
    float S1  = blockReduceSum(s1l, red);
    float MBd = blockReduceSum(mbl, red);
    if (tid == 0) {
        part1[b * NE + e] = S1 + (float)DD * misc[0];
        part2[b * NE + e] = S2q + 2.f * MBd + (float)DD * misc[1];
    }
}

// ---------------- finalize edge BN scale/shift ----------------
__global__ void edge_finalize_kernel(const float* __restrict__ p1, const float* __restrict__ p2,
                                     const float* __restrict__ w, const float* __restrict__ bb,
                                     float* sc, float* sh)
{
    int e = blockIdx.x * blockDim.x + threadIdx.x;
    if (e >= NE) return;
    float s1 = 0.f, s2 = 0.f;
    for (int b = 0; b < BB; b++) { s1 += p1[b * NE + e]; s2 += p2[b * NE + e]; }
    const float cnt = (float)(BB * DD * CC);
    float mean = s1 / cnt;
    float var = s2 / cnt - mean * mean;
    float r = rsqrtf(var + BN_EPS);
    float scale = w[e] * r;
    sc[e] = scale;
    sh[e] = bb[e] - mean * scale;
}

__global__ void fe_affine_kernel(float* __restrict__ fe, const float* __restrict__ sc,
                                 const float* __restrict__ sh)
{
    int idx = blockIdx.x * blockDim.x + threadIdx.x;
    if (idx >= BB * NE * CC) return;
    int e = (idx >> 9) % NE;
    fe[idx] = fe[idx] * sc[e] + sh[e];
}

// BN stats over (B,C) per feature f; data layout [B, F, 512]
__global__ void bnstat_bc_kernel(const float* __restrict__ data, int F,
                                 const float* __restrict__ w, const float* __restrict__ bb,
                                 float* sc, float* sh)
{
    int f = blockIdx.x;
    float s = 0.f, sq = 0.f;
    for (int b = 0; b < BB; b++) {
        const float* p = data + ((size_t)b * F + f) * CC;
        for (int c = threadIdx.x; c < CC; c += blockDim.x) { float v = p[c]; s += v; sq += v * v; }
    }
    __shared__ float red[32];
    s = blockReduceSum(s, red);
    sq = blockReduceSum(sq, red);
    if (threadIdx.x == 0) {
        float mean = s / 2048.f;
        float var = sq / 2048.f - mean * mean;
        float r = rsqrtf(var + BN_EPS);
        float scale = w[f] * r;
        sc[f] = scale;
        sh[f] = bb[f] - mean * scale;
    }
}

__global__ void fe_update_kernel(float* __restrict__ fe, const float* __restrict__ m,
                                 const float* __restrict__ sc, const float* __restrict__ sh)
{
    int idx = blockIdx.x * blockDim.x + threadIdx.x;
    if (idx >= BB * NE * CC) return;
    int e = (idx >> 9) % NE;
    fe[idx] += fmaxf(m[idx] * sc[e] + sh[e], 0.f);
}

__global__ void agg_kernel(const float* __restrict__ fe, const float* __restrict__ ui,
                           const float* __restrict__ uj, float* __restrict__ agg)
{
    int idx = blockIdx.x * blockDim.x + threadIdx.x;
    if (idx >= BB * NN_ * CC) return;
    int c = idx & 511;
    int i = (idx >> 9) % NN_;
    int b = idx / (NN_ * CC);
    const float* fer = fe + ((size_t)b * NE + i * NN_) * CC + c;
    float sw = 0.f, swu = 0.f;
    for (int j = 0; j < NN_; j++) {
        float f = fer[(size_t)j * CC];
        float s = 1.f / (1.f + __expf(-f));
        float wv = __expf(s);
        sw += wv;
        swu += wv * uj[(b * NN_ + j) * CC + c];
    }
    agg[idx] = ui[idx] + swu / (sw * (float)NN_);
}

__global__ void fv_update_kernel(float* __restrict__ fv, const float* __restrict__ agg,
                                 const float* __restrict__ sc, const float* __restrict__ sh)
{
    int idx = blockIdx.x * blockDim.x + threadIdx.x;
    if (idx >= BB * NN_ * CC) return;
    int i = (idx >> 9) % NN_;
    fv[idx] += fmaxf(agg[idx] * sc[i] + sh[i], 0.f);
}

// ---------------- final SC cosine similarities ----------------
__global__ void sc_kernel(const float* __restrict__ fv, const float* __restrict__ mainsc,
                          const float* __restrict__ subsc, float* __restrict__ out)
{
    int o = blockIdx.x, b = blockIdx.y;
    int node;
    const float* anchor;
    if (o < NN_) { node = o; anchor = mainsc + (size_t)o * CC; }
    else { node = c_subidx[o - NN_]; anchor = subsc + (size_t)(o - NN_) * CC; }
    const float* fp = fv + ((size_t)b * NN_ + node) * CC;
    float dot = 0.f, nv = 0.f, na = 0.f;
    for (int c = threadIdx.x; c < CC; c += blockDim.x) {
        float f = fp[c], a = fmaxf(anchor[c], 0.f);
        dot += f * a; nv += f * f; na += a * a;
    }
    __shared__ float red[32];
    dot = blockReduceSum(dot, red);
    nv = blockReduceSum(nv, red);
    na = blockReduceSum(na, red);
    if (threadIdx.x == 0)
        out[b * 41 + o] = dot / (fmaxf(sqrtf(nv), 1e-12f) * fmaxf(sqrtf(na), 1e-12f));
}

// ==================================================================================
extern "C" void kernel_launch(void* const* d_in, const int* in_sizes, int n_in,
                              void* d_out, int out_size)
{
    const float* x       = (const float*)d_in[0];
    const float* nb_W    = (const float*)d_in[1];
    const float* nb_b    = (const float*)d_in[2];
    const float* nb_bnw  = (const float*)d_in[3];
    const float* nb_bnb  = (const float*)d_in[4];
    const float* fam_qW  = (const float*)d_in[5];
    const float* fam_qb  = (const float*)d_in[6];
    const float* fam_kW  = (const float*)d_in[7];
    const float* fam_kb  = (const float*)d_in[8];
    const float* fam_vW  = (const float*)d_in[9];
    const float* fam_vb  = (const float*)d_in[10];
    const float* arm_qW  = (const float*)d_in[11];
    const float* arm_qb  = (const float*)d_in[12];
    const float* arm_kW  = (const float*)d_in[13];
    const float* arm_kb  = (const float*)d_in[14];
    const float* arm_vW  = (const float*)d_in[15];
    const float* arm_vb  = (const float*)d_in[16];
    const float* ep_W    = (const float*)d_in[17];
    const float* ep_b    = (const float*)d_in[18];
    const float* gem_bnw = (const float*)d_in[19];
    const float* gem_bnb = (const float*)d_in[20];
    const float* gnn_uW  = (const float*)d_in[21];
    const float* gnn_vW  = (const float*)d_in[22];
    const float* gnn_aW  = (const float*)d_in[23];
    const float* gnn_bW  = (const float*)d_in[24];
    const float* gnn_eW  = (const float*)d_in[25];
    const float* gnn_bnvw = (const float*)d_in[26];
    const float* gnn_bnvb = (const float*)d_in[27];
    const float* gnn_bnew = (const float*)d_in[28];
    const float* gnn_bneb = (const float*)d_in[29];
    const float* main_sc = (const float*)d_in[30];
    const float* sub_sc  = (const float*)d_in[31];
    float* out = (float*)d_out;

    float* S = nullptr;
    cudaGetSymbolAddress((void**)&S, g_scratch);
    int* pairs = nullptr;
    cudaGetSymbolAddress((void**)&pairs, g_pairs);

    size_t off = 0;
    auto take = [&](size_t n) { float* p = S + off; off += (n + 3) & ~(size_t)3; return p; };
    float* tmp_  = take((size_t)NN_ * BD * CC);
    float* fu_   = take((size_t)BB * NN_ * DD * CC);
    float* feat_ = take((size_t)BB * ND * CC);
    float* VP_   = take((size_t)BB * ND * CC);
    float* q_    = take((size_t)BB * ND * C2);
    float* Qb_   = take((size_t)BB * ND * C2);
    float* Kb_   = take((size_t)BB * ND * C2);
    float* dots_ = take((size_t)BB * ND * ND);
    float* fe_   = take((size_t)BB * NE * CC);
    float* el_   = take((size_t)BB * NE * CC);
    float* attn_ = take((size_t)BB * ND * DD);
    float* MMT_  = take((size_t)BB * NN_ * DD * DD);
    float* kb_   = take((size_t)BB * DD * C2);
    float* vb_   = take((size_t)BB * DD * CC);
    float* fv_   = take((size_t)BB * NN_ * CC);
    float* W2_   = take((size_t)CC * CC);
    float* csbuf_ = take((size_t)BB * NN_ * NN_ * DD);
    float* nmean_ = take(NN_ * CC);
    float* nrstd_ = take(NN_ * CC);
    float* Ms_   = take(MR);
    float* Mb_   = take(MR);
    float* part1_ = take(BB * NE);
    float* part2_ = take(BB * NE);
    float* esc_  = take(NE);
    float* esh_  = take(NE);
    float* vi_   = take((size_t)BB * NN_ * CC);
    float* vj_   = take((size_t)BB * NN_ * CC);
    float* ui_   = take((size_t)BB * NN_ * CC);
    float* uj_   = take((size_t)BB * NN_ * CC);
    float* agg_  = take((size_t)BB * NN_ * CC);
    float* bias2_ = take(CC);
    float* misc_ = take(2);
    float* emsc_ = take(NE);
    float* emsh_ = take(NE);
    float* nvsc_ = take(NN_);
    float* nvsh_ = take(NN_);

    // fast path (K % 16 == 0), big grids
    auto fast_nt = [](const float* A, size_t sA, const float* Bm, size_t sB,
                      float* Cc, size_t sC, const float* bias, size_t sBias,
                      int M, int Nn, int K, int batch, float alpha) {
        dim3 g((Nn + 63) / 64, (M + 127) / 128, batch);
        gemm_fast<true, 0><<<g, 256>>>(A, sA, Bm, sB, Cc, sC, bias, sBias, M, Nn, K, alpha,
                                       nullptr, nullptr);
    };
    // small path (any K), small grids
    auto small_nt = [](const float* A, size_t sA, const float* Bm, size_t sB,
                       float* Cc, size_t sC, const float* bias, size_t sBias,
                       int M, int Nn, int K, int batch, float alpha) {
        dim3 g((Nn + 31) / 32, (M + 31) / 32, batch);
        gemm_small<true><<<g, 256>>>(A, sA, Bm, sB, Cc, sC, bias, sBias, M, Nn, K, alpha);
    };
    auto small_nn = [](const float* A, size_t sA, const float* Bm, size_t sB,
                       float* Cc, size_t sC, const float* bias, size_t sBias,
                       int M, int Nn, int K, int batch, float alpha) {
        dim3 g((Nn + 31) / 32, (M + 31) / 32, batch);
        gemm_small<false><<<g, 256>>>(A, sA, Bm, sB, Cc, sC, bias, sBias, M, Nn, K, alpha);
    };

    pair_init_kernel<<<(NPAIR + 255) / 256, 256>>>(pairs);

    // ---- precompute W2 = ep_W @ arm_vW, bias2 = ep_W @ arm_vb, ep_b sums ----
    small_nn(ep_W, 0, arm_vW, 0, W2_, 0, nullptr, 0, CC, CC, CC, 1, 1.f);
    misc_kernel<<<1, 512>>>(ep_W, arm_vb, ep_b, bias2_, misc_);

    // ---- node blocks: tmp[n] = x @ nb_W[n]^T + nb_b[n]; BN+relu+GAP fused ----
    fast_nt(x, 0, nb_W, (size_t)CC * CC, tmp_, (size_t)BD * CC, nb_b, CC,
            BD, CC, CC, NN_, 1.f);
    bnstat_node_kernel<<<(NN_ * CC + 255) / 256, 256>>>(tmp_, nmean_, nrstd_);
    node_apply_fused<<<(BB * NN_ * CC + 255) / 256, 256>>>(tmp_, nmean_, nrstd_,
                                                           nb_bnw, nb_bnb, fu_, fv_);

    // ---- FAM cross attention ----
    small_nt(x, 0, fam_kW, 0, kb_, 0, fam_kb, 0, BD, C2, CC, 1, 1.f);
    small_nt(x, 0, fam_vW, 0, vb_, 0, fam_vb, 0, BD, CC, CC, 1, 1.f);
    fast_nt(fu_, 0, fam_qW, 0, q_, 0, fam_qb, 0, MR, C2, CC, 1, 1.f);
    small_nt(q_, (size_t)ND * C2, kb_, (size_t)DD * C2, attn_, (size_t)ND * DD,
             nullptr, 0, ND, DD, C2, BB, SCALE);
    softmax49_kernel<<<(MR + 7) / 8, 256>>>(attn_, MR);
    small_nn(attn_, (size_t)ND * DD, vb_, (size_t)DD * CC, feat_, (size_t)ND * CC,
             nullptr, 0, ND, CC, DD, BB, 1.f);

    // ---- ARM projections (V folded with ep_W into VP) ----
    fast_nt(feat_, 0, arm_qW, 0, Qb_, 0, arm_qb, 0, MR, C2, CC, 1, 1.f);
    fast_nt(feat_, 0, arm_kW, 0, Kb_, 0, arm_kb, 0, MR, C2, CC, 1, 1.f);
    fast_nt(feat_, 0, W2_, 0, VP_, 0, bias2_, 0, MR, CC, CC, 1, 1.f);

    // ---- pairwise dots (all edges at once): [1323,1323] per batch ----
    fast_nt(Qb_, (size_t)ND * C2, Kb_, (size_t)ND * C2, dots_, (size_t)ND * ND,
            nullptr, 0, ND, ND, C2, BB, SCALE);

    // ---- per-(b,i): M M^T, row sums, M@ep_b ----
    small_nt(VP_, (size_t)DD * CC, VP_, (size_t)DD * CC, MMT_, (size_t)DD * DD,
             nullptr, 0, DD, DD, CC, BB * NN_, 1.f);
    msmb_kernel<<<(MR + 7) / 8, 256>>>(VP_, ep_b, Ms_, Mb_);

    // ---- per-edge: softmax + BN-stat partials; export colsum/D for fe GEMM ----
    {
        dim3 g(NE, BB);
        edge_kernel<<<g, 256>>>(dots_, MMT_, Ms_, Mb_, misc_, pairs, part1_, part2_, csbuf_);
    }
    // fe[b, i*27+j, :] = (cs/D) @ VP_(b,i) + ep_b   (batched over (b,i))
    small_nn(csbuf_, (size_t)NN_ * DD, VP_, (size_t)DD * CC, fe_, (size_t)NN_ * CC,
             ep_b, 0, NN_, CC, DD, BB * NN_, 1.f);
    edge_finalize_kernel<<<(NE + 255) / 256, 256>>>(part1_, part2_, gem_bnw, gem_bnb, esc_, esh_);
    fe_affine_kernel<<<(BB * NE * CC + 255) / 256, 256>>>(fe_, esc_, esh_);

    // ---- 2 GatedGNN layers ----
    for (int l = 0; l < 2; l++) {
        const float* aW = gnn_aW + (size_t)l * CC * CC;
        const float* bW = gnn_bW + (size_t)l * CC * CC;
        const float* uW = gnn_uW + (size_t)l * CC * CC;
        const float* vW = gnn_vW + (size_t)l * CC * CC;
        const float* eW = gnn_eW + (size_t)l * CC * CC;
        small_nt(fv_, 0, aW, 0, vi_, 0, nullptr, 0, BB * NN_, CC, CC, 1, 1.f);
        small_nt(fv_, 0, bW, 0, vj_, 0, nullptr, 0, BB * NN_, CC, CC, 1, 1.f);
        small_nt(fv_, 0, uW, 0, ui_, 0, nullptr, 0, BB * NN_, CC, CC, 1, 1.f);
        small_nt(fv_, 0, vW, 0, uj_, 0, nullptr, 0, BB * NN_, CC, CC, 1, 1.f);
        // el = fe @ eW^T + vi[b,i] + vj[b,j]  (fused epilogue)
        {
            dim3 g((CC + 63) / 64, (BB * NE + 127) / 128, 1);
            gemm_fast<true, 1><<<g, 256>>>(fe_, 0, eW, 0, el_, 0, nullptr, 0,
                                           BB * NE, CC, CC, 1.f, vi_, vj_);
        }
        int tot = BB * NE * CC;
        bnstat_bc_kernel<<<NE, 256>>>(el_, NE, gnn_bnew + (size_t)l * NE, gnn_bneb + (size_t)l * NE,
                                      emsc_, emsh_);
        fe_update_kernel<<<(tot + 255) / 256, 256>>>(fe_, el_, emsc_, emsh_);
        agg_kernel<<<(BB * NN_ * CC + 255) / 256, 256>>>(fe_, ui_, uj_, agg_);
        bnstat_bc_kernel<<<NN_, 256>>>(agg_, NN_, gnn_bnvw + (size_t)l * NN_,
                                       gnn_bnvb + (size_t)l * NN_, nvsc_, nvsh_);
        fv_update_kernel<<<(BB * NN_ * CC + 255) / 256, 256>>>(fv_, agg_, nvsc_, nvsh_);
    }

    // ---- SC cosine outputs ----
    {
        dim3 g(41, BB);
        sc_kernel<<<g, 128>>>(fv_, main_sc, sub_sc, out);
    }
}

// round 10
// speedup vs baseline: 1.4303x; 1.0326x over previous
#include <cuda_runtime.h>
#include <math.h>

#define BB 4
#define DD 49
#define CC 512
#define C2 256
#define NN_ 27
#define NE 729      // N*N
#define ND 1323     // N*D
#define BD 196      // B*D
#define MR 5292     // B*N*D
#define NPAIR 1225  // DD*(DD+1)/2
#define VLD 2048    // stride of concatenated GNN node projections
#define BN_EPS 1e-5f
#define SCALE 0.0625f   // 256^-0.5

__device__ float g_scratch[33000000];
__device__ int g_pairs[NPAIR];

__constant__ int c_subidx[14] = {0,0,1,1,2,2,4,4,7,7,8,8,11,11};

// ---------------- utilities ----------------
__device__ __forceinline__ float blockReduceSum(float v, float* sh) {
    __syncthreads();
    int lane = threadIdx.x & 31, w = threadIdx.x >> 5;
#pragma unroll
    for (int o = 16; o; o >>= 1) v += __shfl_xor_sync(0xffffffffu, v, o);
    if (lane == 0) sh[w] = v;
    __syncthreads();
    float r = 0.f;
    if (w == 0) {
        int nw = (blockDim.x + 31) >> 5;
        r = (lane < nw) ? sh[lane] : 0.f;
#pragma unroll
        for (int o = 16; o; o >>= 1) r += __shfl_xor_sync(0xffffffffu, r, o);
    }
    return r;
}

// =============== gemm_f2: 128x128x16 tile, 256 thr, 8x8/thread, K%16==0 ===============
// TRANSB=true : B is [N,K] row-major with leading dim ldb; C = alpha*A@B^T + bias
// TRANSB=false: B is [K,N] row-major with leading dim ldb; C = alpha*A@B + bias
template<bool TRANSB>
__global__ void __launch_bounds__(256, 2)
gemm_f2(const float* __restrict__ A, int lda, size_t sA,
        const float* __restrict__ Bm, int ldb, size_t sB,
        float* __restrict__ Cm, int ldc, size_t sC,
        const float* __restrict__ bias, size_t sBias,
        int M, int Nn, int K, float alpha)
{
    const int BK = 16;
    int bz = blockIdx.z;
    A  += (size_t)bz * sA;
    Bm += (size_t)bz * sB;
    Cm += (size_t)bz * sC;
    int m0 = blockIdx.y * 128, n0 = blockIdx.x * 128;

    __shared__ float As[BK][128];
    __shared__ float Bs[BK][128];

    int tid = threadIdx.x;
    int tx = tid & 15, ty = tid >> 4;

    // A: thread loads 2 float4 along K for one m-row
    int am = tid >> 1, akq = (tid & 1) << 3;
    bool aok = (m0 + am) < M;
    const float* Ap = A + (size_t)(m0 + am) * lda + akq;

    // B mappings
    int bn = tid >> 1, bkq = (tid & 1) << 3;          // TRANSB
    int nk0 = tid >> 5, nq0 = (tid & 31) << 2;        // NN: elem 0 (k rows 0..7)
    int nk1 = nk0 + 8;                                // NN: elem 1 (k rows 8..15)
    const float* Bp;
    bool bok;
    if (TRANSB) {
        bok = (n0 + bn) < Nn;
        Bp = Bm + (size_t)(n0 + bn) * ldb + bkq;
    } else {
        bok = (n0 + nq0 + 3) < Nn;
        Bp = Bm + n0 + nq0;
    }
    const float4 z4 = make_float4(0.f, 0.f, 0.f, 0.f);

    float acc[8][8];
#pragma unroll
    for (int i = 0; i < 8; i++)
#pragma unroll
        for (int j = 0; j < 8; j++) acc[i][j] = 0.f;

    auto ldA = [&](int k0, float4& x, float4& y) {
        if (aok) { x = *(const float4*)(Ap + k0); y = *(const float4*)(Ap + k0 + 4); }
        else { x = z4; y = z4; }
    };
    auto ldB = [&](int k0, float4& x, float4& y) {
        if (TRANSB) {
            if (bok) { x = *(const float4*)(Bp + k0); y = *(const float4*)(Bp + k0 + 4); }
            else { x = z4; y = z4; }
        } else {
            const float* r0 = Bp + (size_t)(k0 + nk0) * ldb;
            const float* r1 = Bp + (size_t)(k0 + nk1) * ldb;
            if (bok) { x = *(const float4*)r0; y = *(const float4*)r1; }
            else {
                x = z4; y = z4;
                int gn = n0 + nq0;
                if (gn < Nn)     { x.x = r0[0]; y.x = r1[0]; }
                if (gn + 1 < Nn) { x.y = r0[1]; y.y = r1[1]; }
                if (gn + 2 < Nn) { x.z = r0[2]; y.z = r1[2]; }
            }
        }
    };
    auto stAB = [&](float4 ax, float4 ay, float4 bx, float4 by) {
        As[akq + 0][am] = ax.x; As[akq + 1][am] = ax.y;
        As[akq + 2][am] = ax.z; As[akq + 3][am] = ax.w;
        As[akq + 4][am] = ay.x; As[akq + 5][am] = ay.y;
        As[akq + 6][am] = ay.z; As[akq + 7][am] = ay.w;
        if (TRANSB) {
            Bs[bkq + 0][bn] = bx.x; Bs[bkq + 1][bn] = bx.y;
            Bs[bkq + 2][bn] = bx.z; Bs[bkq + 3][bn] = bx.w;
            Bs[bkq + 4][bn] = by.x; Bs[bkq + 5][bn] = by.y;
            Bs[bkq + 6][bn] = by.z; Bs[bkq + 7][bn] = by.w;
        } else {
            *(float4*)&Bs[nk0][nq0] = bx;
            *(float4*)&Bs[nk1][nq0] = by;
        }
    };

    int KT = K >> 4;
    {
        float4 ax, ay, bx, by;
        ldA(0, ax, ay); ldB(0, bx, by);
        stAB(ax, ay, bx, by);
    }
    __syncthreads();

    for (int kt = 0; kt < KT; kt++) {
        float4 nax, nay, nbx, nby;
        bool more = (kt + 1) < KT;
        if (more) {
            int k0 = (kt + 1) << 4;
            ldA(k0, nax, nay); ldB(k0, nbx, nby);
        }
#pragma unroll
        for (int kk = 0; kk < BK; kk++) {
            float4 a0 = *(const float4*)&As[kk][ty << 3];
            float4 a1 = *(const float4*)&As[kk][(ty << 3) + 4];
            float4 b0 = *(const float4*)&Bs[kk][tx << 3];
            float4 b1 = *(const float4*)&Bs[kk][(tx << 3) + 4];
            float a[8] = {a0.x, a0.y, a0.z, a0.w, a1.x, a1.y, a1.z, a1.w};
            float b[8] = {b0.x, b0.y, b0.z, b0.w, b1.x, b1.y, b1.z, b1.w};
#pragma unroll
            for (int i = 0; i < 8; i++)
#pragma unroll
                for (int j = 0; j < 8; j++)
                    acc[i][j] += a[i] * b[j];
        }
        __syncthreads();
        if (more) { stAB(nax, nay, nbx, nby); }
        __syncthreads();
    }

    const float* bp = bias ? (bias + (size_t)bz * sBias) : nullptr;
#pragma unroll
    for (int i = 0; i < 8; i++) {
        int gm = m0 + (ty << 3) + i;
        if (gm >= M) continue;
        float* crow = Cm + (size_t)gm * ldc;
#pragma unroll
        for (int j = 0; j < 8; j++) {
            int gn = n0 + (tx << 3) + j;
            if (gn >= Nn) continue;
            float v = acc[i][j] * alpha;
            if (bp) v += bp[gn];
            crow[gn] = v;
        }
    }
}

// =============== old fast GEMM: 128x64, 8x4/thread (kept for N=256 / EPI paths) =======
// EPI==1: epilogue adds evi[(b,i),c] + evj[(b,j),c] with stride evld.
template<bool TRANSB, int EPI>
__global__ void __launch_bounds__(256, 2)
gemm_fast(const float* __restrict__ A, size_t sA,
          const float* __restrict__ Bm, size_t sB,
          float* __restrict__ Cm, size_t sC,
          const float* __restrict__ bias, size_t sBias,
          int M, int Nn, int K, float alpha,
          const float* __restrict__ evi, const float* __restrict__ evj, int evld)
{
    const int BK = 16;
    int bz = blockIdx.z;
    A  += (size_t)bz * sA;
    Bm += (size_t)bz * sB;
    Cm += (size_t)bz * sC;
    int m0 = blockIdx.y * 128, n0 = blockIdx.x * 64;

    __shared__ float As[BK][128];
    __shared__ float Bs[BK][64];

    int tid = threadIdx.x;
    int tx = tid & 15, ty = tid >> 4;

    int ar0 = tid >> 2;
    int ar1 = ar0 + 64;
    int ak  = (tid & 3) << 2;
    int gm0 = m0 + ar0, gm1 = m0 + ar1;
    bool a0ok = gm0 < M, a1ok = gm1 < M;
    const float* Arow0 = A + (size_t)gm0 * K + ak;
    const float* Arow1 = A + (size_t)gm1 * K + ak;

    int bn = tid >> 2, bkq = (tid & 3) << 2;
    bool bok = (n0 + bn) < Nn;
    const float* Bptr = Bm + (size_t)(n0 + bn) * K + bkq;

    const float4 z4 = make_float4(0.f, 0.f, 0.f, 0.f);

    float acc[8][4];
#pragma unroll
    for (int i = 0; i < 8; i++)
#pragma unroll
        for (int j = 0; j < 4; j++) acc[i][j] = 0.f;

    auto store = [&](float4 a0, float4 a1, float4 b) {
        As[ak + 0][ar0] = a0.x; As[ak + 1][ar0] = a0.y;
        As[ak + 2][ar0] = a0.z; As[ak + 3][ar0] = a0.w;
        As[ak + 0][ar1] = a1.x; As[ak + 1][ar1] = a1.y;
        As[ak + 2][ar1] = a1.z; As[ak + 3][ar1] = a1.w;
        Bs[bkq + 0][bn] = b.x; Bs[bkq + 1][bn] = b.y;
        Bs[bkq + 2][bn] = b.z; Bs[bkq + 3][bn] = b.w;
    };

    int KT = K >> 4;
    {
        float4 pa0 = a0ok ? *(const float4*)Arow0 : z4;
        float4 pa1 = a1ok ? *(const float4*)Arow1 : z4;
        float4 pb  = bok ? *(const float4*)Bptr : z4;
        store(pa0, pa1, pb);
    }
    __syncthreads();

    for (int kt = 0; kt < KT; kt++) {
        float4 na0, na1, nb;
        bool more = (kt + 1) < KT;
        if (more) {
            int k0 = (kt + 1) << 4;
            na0 = a0ok ? *(const float4*)(Arow0 + k0) : z4;
            na1 = a1ok ? *(const float4*)(Arow1 + k0) : z4;
            nb  = bok ? *(const float4*)(Bptr + k0) : z4;
        }
#pragma unroll
        for (int kk = 0; kk < BK; kk++) {
            float4 b4 = *(const float4*)&Bs[kk][tx << 2];
            float4 aA = *(const float4*)&As[kk][ty << 3];
            float4 aB = *(const float4*)&As[kk][(ty << 3) + 4];
            float a[8] = {aA.x, aA.y, aA.z, aA.w, aB.x, aB.y, aB.z, aB.w};
            float bv[4] = {b4.x, b4.y, b4.z, b4.w};
#pragma unroll
            for (int i = 0; i < 8; i++)
#pragma unroll
                for (int j = 0; j < 4; j++)
                    acc[i][j] += a[i] * bv[j];
        }
        __syncthreads();
        if (more) store(na0, na1, nb);
        __syncthreads();
    }

    const float* bp = bias ? (bias + (size_t)bz * sBias) : nullptr;
#pragma unroll
    for (int i = 0; i < 8; i++) {
        int gm = m0 + (ty << 3) + i;
        if (gm >= M) continue;
        float* crow = Cm + (size_t)gm * Nn;
        const float* vip = nullptr; const float* vjp = nullptr;
        if (EPI == 1) {
            int b = gm / NE; int e = gm - b * NE;
            int ii = e / NN_; int jj = e - ii * NN_;
            vip = evi + (size_t)(b * NN_ + ii) * evld;
            vjp = evj + (size_t)(b * NN_ + jj) * evld;
        }
#pragma unroll
        for (int j = 0; j < 4; j++) {
            int gn = n0 + (tx << 2) + j;
            if (gn >= Nn) continue;
            float v = acc[i][j] * alpha;
            if (bp) v += bp[gn];
            if (EPI == 1) v += vip[gn] + vjp[gn];
            crow[gn] = v;
        }
    }
}

// =============== SMALL tiled GEMM (any K): 32x32 tile, 2x2/thread, with ld params =====
// EPI==2: v = (acc*alpha + bias) * esc[e] + esh[e],  e = (bz%NN_)*NN_ + gm
template<bool TRANSB, int EPI>
__global__ void gemm_small(const float* __restrict__ A, int lda, size_t sA,
                           const float* __restrict__ Bm, int ldb, size_t sB,
                           float* __restrict__ Cm, int ldc, size_t sC,
                           const float* __restrict__ bias, size_t sBias,
                           int M, int Nn, int K, float alpha,
                           const float* __restrict__ esc, const float* __restrict__ esh)
{
    const int BK = 16;
    int bz = blockIdx.z;
    A  += (size_t)bz * sA;
    Bm += (size_t)bz * sB;
    Cm += (size_t)bz * sC;
    int m0 = blockIdx.y * 32, n0 = blockIdx.x * 32;

    __shared__ float As[BK][33];
    __shared__ float Bs[BK][33];

    int tid = threadIdx.x;
    int ty = tid >> 4, tx = tid & 15;
    float acc[2][2] = {};

    for (int k0 = 0; k0 < K; k0 += BK) {
#pragma unroll
        for (int t = 0; t < 2; t++) {
            int e = tid + t * 256;
            int m = e >> 4, k = e & 15;
            float v = 0.f;
            int gm = m0 + m, gk = k0 + k;
            if (gm < M && gk < K) v = A[(size_t)gm * lda + gk];
            As[k][m] = v;
        }
#pragma unroll
        for (int t = 0; t < 2; t++) {
            int e = tid + t * 256;
            float v = 0.f;
            if (TRANSB) {
                int n = e >> 4, k = e & 15;
                int gn = n0 + n, gk = k0 + k;
                if (gn < Nn && gk < K) v = Bm[(size_t)gn * ldb + gk];
                Bs[k][n] = v;
            } else {
                int k = e >> 5, n = e & 31;
                int gk = k0 + k, gn = n0 + n;
                if (gk < K && gn < Nn) v = Bm[(size_t)gk * ldb + gn];
                Bs[k][n] = v;
            }
        }
        __syncthreads();
#pragma unroll
        for (int kk = 0; kk < BK; kk++) {
            float a0 = As[kk][2 * ty], a1 = As[kk][2 * ty + 1];
            float b0 = Bs[kk][2 * tx], b1 = Bs[kk][2 * tx + 1];
            acc[0][0] += a0 * b0; acc[0][1] += a0 * b1;
            acc[1][0] += a1 * b0; acc[1][1] += a1 * b1;
        }
        __syncthreads();
    }

    const float* bp = bias ? (bias + (size_t)bz * sBias) : nullptr;
#pragma unroll
    for (int i = 0; i < 2; i++) {
        int gm = m0 + 2 * ty + i;
        if (gm >= M) continue;
#pragma unroll
        for (int j = 0; j < 2; j++) {
            int gn = n0 + 2 * tx + j;
            if (gn >= Nn) continue;
            float v = acc[i][j] * alpha;
            if (bp) v += bp[gn];
            if (EPI == 2) {
                int i_ = bz % NN_;
                int e = i_ * NN_ + gm;
                v = v * esc[e] + esh[e];
            }
            Cm[(size_t)gm * ldc + gn] = v;
        }
    }
}

// ---------------- pair table for symmetric trace ----------------
__global__ void pair_init_kernel(int* pairs)
{
    int t = blockIdx.x * blockDim.x + threadIdx.x;
    if (t >= NPAIR) return;
    int p = 0, base = 0;
    while (base + (DD - p) <= t) { base += DD - p; p++; }
    int q = p + (t - base);
    pairs[t] = (p << 8) | q;
}

// ---------------- dedicated MMT gram kernel: per-(b,i), upper triangle only ----------
__global__ void mmt_kernel(const float* __restrict__ VP, const int* __restrict__ pairs,
                           float* __restrict__ MMT)
{
    int bi = blockIdx.x;  // b*NN_+i
    const float* Mp = VP + (size_t)bi * DD * CC;
    __shared__ float sh[DD][36];
    int tid = threadIdx.x;

    int pp[5], qq[5];
    float4 acc[5];
#pragma unroll
    for (int s = 0; s < 5; s++) {
        int t = tid + s * 256;
        acc[s] = make_float4(0.f, 0.f, 0.f, 0.f);
        if (t < NPAIR) { int pq = pairs[t]; pp[s] = pq >> 8; qq[s] = pq & 255; }
        else { pp[s] = -1; qq[s] = 0; }
    }

    for (int k0 = 0; k0 < CC; k0 += 32) {
        __syncthreads();
        for (int e = tid; e < DD * 8; e += 256) {
            int r = e >> 3, kq = (e & 7) << 2;
            *(float4*)&sh[r][kq] = *(const float4*)(Mp + (size_t)r * CC + k0 + kq);
        }
        __syncthreads();
#pragma unroll
        for (int s = 0; s < 5; s++) {
            if (pp[s] < 0) continue;
            const float* rp = sh[pp[s]];
            const float* rq = sh[qq[s]];
#pragma unroll
            for (int kk = 0; kk < 32; kk += 4) {
                float4 a = *(const float4*)(rp + kk);
                float4 b = *(const float4*)(rq + kk);
                acc[s].x += a.x * b.x; acc[s].y += a.y * b.y;
                acc[s].z += a.z * b.z; acc[s].w += a.w * b.w;
            }
        }
    }
#pragma unroll
    for (int s = 0; s < 5; s++) {
        if (pp[s] < 0) continue;
        float r = (acc[s].x + acc[s].y) + (acc[s].z + acc[s].w);
        MMT[(size_t)bi * DD * DD + pp[s] * DD + qq[s]] = r;
    }
}

// ---------------- misc precompute ----------------
__global__ void misc_kernel(const float* __restrict__ epW, const float* __restrict__ armvb,
                            const float* __restrict__ epb, float* bias2, float* misc)
{
    int t = threadIdx.x;  // 512
    float s = 0.f;
    for (int c = 0; c < CC; c++) s += epW[(size_t)t * CC + c] * armvb[c];
    bias2[t] = s;
    __shared__ float red[32];
    float v = epb[t];
    float s1 = blockReduceSum(v, red);
    float s2 = blockReduceSum(v * v, red);
    if (t == 0) { misc[0] = s1; misc[1] = s2; }
}

// ---------------- node BN stats over (B,D) per (n,c) ----------------
__global__ void bnstat_node_kernel(const float* __restrict__ tmp, float* mean, float* rstd)
{
    int idx = blockIdx.x * blockDim.x + threadIdx.x;
    if (idx >= NN_ * CC) return;
    int n = idx >> 9, c = idx & 511;
    const float* p = tmp + (size_t)n * BD * CC + c;
    float s = 0.f, sq = 0.f;
    for (int r = 0; r < BD; r++) { float v = p[(size_t)r * CC]; s += v; sq += v * v; }
    float m = s / (float)BD;
    mean[idx] = m;
    rstd[idx] = rsqrtf(sq / (float)BD - m * m + BN_EPS);
}

// ---------------- fused: f_u = relu(BN(tmp)) + GAP -> f_v ----------------
__global__ void node_apply_fused(const float* __restrict__ tmp, const float* __restrict__ mean,
                                 const float* __restrict__ rstd, const float* __restrict__ w,
                                 const float* __restrict__ bb,
                                 float* __restrict__ fu, float* __restrict__ fv)
{
    int idx = blockIdx.x * blockDim.x + threadIdx.x;
    if (idx >= BB * NN_ * CC) return;
    int c = idx & 511;
    int n = (idx >> 9) % NN_;
    int b = idx / (NN_ * CC);
    int nc = (n << 9) + c;
    float mu = mean[nc], rs = rstd[nc] * w[nc], bias = bb[nc];
    const float* tp = tmp + ((size_t)n * BD + b * DD) * CC + c;
    float* fp = fu + ((size_t)(b * NN_ + n) * DD) * CC + c;
    float s = 0.f;
    for (int d = 0; d < DD; d++) {
        float v = fmaxf((tp[(size_t)d * CC] - mu) * rs + bias, 0.f);
        fp[(size_t)d * CC] = v;
        s += v;
    }
    fv[idx] = s * (1.f / (float)DD);
}

// ---------------- zero pad rows 49..63 of vb_p ----------------
__global__ void vbp_zero_kernel(float* __restrict__ vbp)
{
    int idx = blockIdx.x * blockDim.x + threadIdx.x;
    if (idx >= BB * 15 * CC) return;
    int c = idx % CC;
    int r = (idx / CC) % 15;
    int b = idx / (15 * CC);
    vbp[((size_t)b * 64 + 49 + r) * CC + c] = 0.f;
}

// ---------------- softmax over padded rows [*,64], cols 49..63 zeroed ----------------
__global__ void softmax49_kernel(float* __restrict__ data, int rows)
{
    int row = blockIdx.x * 8 + (threadIdx.x >> 5);
    if (row >= rows) return;
    int lane = threadIdx.x & 31;
    float* p = data + (size_t)row * 64;
    float v0 = p[lane];
    float v1 = (lane + 32 < DD) ? p[lane + 32] : -3.4e38f;
    float mx = fmaxf(v0, v1);
#pragma unroll
    for (int o = 16; o; o >>= 1) mx = fmaxf(mx, __shfl_xor_sync(0xffffffffu, mx, o));
    float e0 = __expf(v0 - mx);
    float e1 = (lane + 32 < DD) ? __expf(v1 - mx) : 0.f;
    float s = e0 + e1;
#pragma unroll
    for (int o = 16; o; o >>= 1) s += __shfl_xor_sync(0xffffffffu, s, o);
    float inv = 1.f / s;
    p[lane] = e0 * inv;
    p[lane + 32] = (lane + 32 < DD) ? e1 * inv : 0.f;
}

// ---------------- Ms (row sums) and Mb (rows @ ep_b) of VP ----------------
__global__ void msmb_kernel(const float* __restrict__ VP, const float* __restrict__ epb,
                            float* __restrict__ Ms, float* __restrict__ Mb)
{
    int row = blockIdx.x * 8 + (threadIdx.x >> 5);
    if (row >= MR) return;
    int lane = threadIdx.x & 31;
    const float* p = VP + (size_t)row * CC;
    float s = 0.f, sb = 0.f;
    for (int c = lane; c < CC; c += 32) { float v = p[c]; s += v; sb += v * epb[c]; }
#pragma unroll
    for (int o = 16; o; o >>= 1) {
        s  += __shfl_xor_sync(0xffffffffu, s, o);
        sb += __shfl_xor_sync(0xffffffffu, sb, o);
    }
    if (lane == 0) { Ms[row] = s; Mb[row] = sb; }
}

// ---------------- per-edge kernel: softmax + BN-stat partials + colsum export --------
__global__ void edge_kernel(const float* __restrict__ dots, const float* __restrict__ MMT,
                            const float* __restrict__ Ms, const float* __restrict__ Mb,
                            const float* __restrict__ misc, const int* __restrict__ pairs,
                            float* __restrict__ part1, float* __restrict__ part2,
                            float* __restrict__ csbuf)
{
    int e = blockIdx.x, b = blockIdx.y;
    int i = e / NN_, j = e % NN_;
    __shared__ float A[DD][52];
    __shared__ float cs[DD];
    __shared__ float red[32];
    int tid = threadIdx.x, lane = tid & 31, w = tid >> 5;

    const float* P = dots + (size_t)b * ND * ND + (size_t)(j * DD) * ND + i * DD;
    for (int d = w; d < DD; d += 8) {
        const float* pr = P + (size_t)d * ND;
        float v0 = pr[lane];
        float v1 = (lane + 32 < DD) ? pr[lane + 32] : -3.4e38f;
        float mx = fmaxf(v0, v1);
#pragma unroll
        for (int o = 16; o; o >>= 1) mx = fmaxf(mx, __shfl_xor_sync(0xffffffffu, mx, o));
        float e0 = __expf(v0 - mx);
        float e1 = (lane + 32 < DD) ? __expf(v1 - mx) : 0.f;
        float s = e0 + e1;
#pragma unroll
        for (int o = 16; o; o >>= 1) s += __shfl_xor_sync(0xffffffffu, s, o);
        float inv = 1.f / s;
        A[d][lane] = e0 * inv;
        if (lane + 32 < DD) A[d][lane + 32] = e1 * inv;
    }
    __syncthreads();

    if (tid < DD) {
        float s = 0.f;
        for (int d = 0; d < DD; d++) s += A[d][tid];
        cs[tid] = s;
    }
    __syncthreads();
    if (tid < 64)
        csbuf[((size_t)(b * NN_ + i) * NN_ + j) * 64 + tid] =
            (tid < DD) ? cs[tid] * (1.f / (float)DD) : 0.f;

    // tr(A^T A * M M^T), both symmetric: upper triangle only
    const float* mmt = MMT + (size_t)(b * NN_ + i) * DD * DD;
    float qa = 0.f;
    for (int t = tid; t < NPAIR; t += 256) {
        int pq = pairs[t];
        int p = pq >> 8, q = pq & 255;
        float s = 0.f;
        for (int d = 0; d < DD; d++) s += A[d][p] * A[d][q];
        float mv = mmt[p * DD + q];
        qa += s * mv * ((p == q) ? 1.f : 2.f);
    }
    int mrow = (b * NN_ + i) * DD;
    float s1l = (tid < DD) ? cs[tid] * Ms[mrow + tid] : 0.f;
    float mbl = (tid < DD) ? cs[tid] * Mb[mrow + tid] : 0.f;
    float S2q = blockReduceSum(qa, red);
    float S1  = blockReduceSum(s1l, red);
    float MBd = blockReduceSum(mbl, red);
    if (tid == 0) {
        part1[b * NE + e] = S1 + (float)DD * misc[0];
        part2[b * NE + e] = S2q + 2.f * MBd + (float)DD * misc[1];
    }
}

// ---------------- finalize edge BN scale/shift ----------------
__global__ void edge_finalize_kernel(const float* __restrict__ p1, const float* __restrict__ p2,
                                     const float* __restrict__ w, const float* __restrict__ bb,
                                     float* sc, float* sh)
{
    int e = blockIdx.x * blockDim.x + threadIdx.x;
    if (e >= NE) return;
    float s1 = 0.f, s2 = 0.f;
    for (int b = 0; b < BB; b++) { s1 += p1[b * NE + e]; s2 += p2[b * NE + e]; }
    const float cnt = (float)(BB * DD * CC);
    float mean = s1 / cnt;
    float var = s2 / cnt - mean * mean;
    float r = rsqrtf(var + BN_EPS);
    float scale = w[e] * r;
    sc[e] = scale;
    sh[e] = bb[e] - mean * scale;
}

// BN stats over (B,C) per feature f; data layout [B, F, 512]
__global__ void bnstat_bc_kernel(const float* __restrict__ data, int F,
                                 const float* __restrict__ w, const float* __restrict__ bb,
                                 float* sc, float* sh)
{
    int f = blockIdx.x;
    float s = 0.f, sq = 0.f;
    for (int b = 0; b < BB; b++) {
        const float* p = data + ((size_t)b * F + f) * CC;
        for (int c = threadIdx.x; c < CC; c += blockDim.x) { float v = p[c]; s += v; sq += v * v; }
    }
    __shared__ float red[32];
    s = blockReduceSum(s, red);
    sq = blockReduceSum(sq, red);
    if (threadIdx.x == 0) {
        float mean = s / 2048.f;
        float var = sq / 2048.f - mean * mean;
        float r = rsqrtf(var + BN_EPS);
        float scale = w[f] * r;
        sc[f] = scale;
        sh[f] = bb[f] - mean * scale;
    }
}

__global__ void fe_update_kernel(float* __restrict__ fe, const float* __restrict__ m,
                                 const float* __restrict__ sc, const float* __restrict__ sh)
{
    int idx = blockIdx.x * blockDim.x + threadIdx.x;
    if (idx >= BB * NE * CC) return;
    int e = (idx >> 9) % NE;
    fe[idx] += fmaxf(m[idx] * sc[e] + sh[e], 0.f);
}

__global__ void agg_kernel(const float* __restrict__ fe, const float* __restrict__ ui,
                           const float* __restrict__ uj, float* __restrict__ agg)
{
    int idx = blockIdx.x * blockDim.x + threadIdx.x;
    if (idx >= BB * NN_ * CC) return;
    int c = idx & 511;
    int i = (idx >> 9) % NN_;
    int b = idx / (NN_ * CC);
    const float* fer = fe + ((size_t)b * NE + i * NN_) * CC + c;
    float sw = 0.f, swu = 0.f;
    for (int j = 0; j < NN_; j++) {
        float f = fer[(size_t)j * CC];
        float s = 1.f / (1.f + __expf(-f));
        float wv = __expf(s);
        sw += wv;
        swu += wv * uj[(size_t)(b * NN_ + j) * VLD + c];
    }
    agg[idx] = ui[(size_t)(b * NN_ + i) * VLD + c] + swu / (sw * (float)NN_);
}

__global__ void fv_update_kernel(float* __restrict__ fv, const float* __restrict__ agg,
                                 const float* __restrict__ sc, const float* __restrict__ sh)
{
    int idx = blockIdx.x * blockDim.x + threadIdx.x;
    if (idx >= BB * NN_ * CC) return;
    int i = (idx >> 9) % NN_;
    fv[idx] += fmaxf(agg[idx] * sc[i] + sh[i], 0.f);
}

// ---------------- final SC cosine similarities ----------------
__global__ void sc_kernel(const float* __restrict__ fv, const float* __restrict__ mainsc,
                          const float* __restrict__ subsc, float* __restrict__ out)
{
    int o = blockIdx.x, b = blockIdx.y;
    int node;
    const float* anchor;
    if (o < NN_) { node = o; anchor = mainsc + (size_t)o * CC; }
    else { node = c_subidx[o - NN_]; anchor = subsc + (size_t)(o - NN_) * CC; }
    const float* fp = fv + ((size_t)b * NN_ + node) * CC;
    float dot = 0.f, nv = 0.f, na = 0.f;
    for (int c = threadIdx.x; c < CC; c += blockDim.x) {
        float f = fp[c], a = fmaxf(anchor[c], 0.f);
        dot += f * a; nv += f * f; na += a * a;
    }
    __shared__ float red[32];
    dot = blockReduceSum(dot, red);
    nv = blockReduceSum(nv, red);
    na = blockReduceSum(na, red);
    if (threadIdx.x == 0)
        out[b * 41 + o] = dot / (fmaxf(sqrtf(nv), 1e-12f) * fmaxf(sqrtf(na), 1e-12f));
}

// ==================================================================================
extern "C" void kernel_launch(void* const* d_in, const int* in_sizes, int n_in,
                              void* d_out, int out_size)
{
    const float* x       = (const float*)d_in[0];
    const float* nb_W    = (const float*)d_in[1];
    const float* nb_b    = (const float*)d_in[2];
    const float* nb_bnw  = (const float*)d_in[3];
    const float* nb_bnb  = (const float*)d_in[4];
    const float* fam_qW  = (const float*)d_in[5];
    const float* fam_qb  = (const float*)d_in[6];
    const float* fam_kW  = (const float*)d_in[7];
    const float* fam_kb  = (const float*)d_in[8];
    const float* fam_vW  = (const float*)d_in[9];
    const float* fam_vb  = (const float*)d_in[10];
    const float* arm_qW  = (const float*)d_in[11];
    const float* arm_qb  = (const float*)d_in[12];
    const float* arm_kW  = (const float*)d_in[13];
    const float* arm_kb  = (const float*)d_in[14];
    const float* arm_vW  = (const float*)d_in[15];
    const float* arm_vb  = (const float*)d_in[16];
    const float* ep_W    = (const float*)d_in[17];
    const float* ep_b    = (const float*)d_in[18];
    const float* gem_bnw = (const float*)d_in[19];
    const float* gem_bnb = (const float*)d_in[20];
    const float* gnn_uW  = (const float*)d_in[21];
    const float* gnn_vW  = (const float*)d_in[22];
    const float* gnn_aW  = (const float*)d_in[23];
    const float* gnn_bW  = (const float*)d_in[24];
    const float* gnn_eW  = (const float*)d_in[25];
    const float* gnn_bnvw = (const float*)d_in[26];
    const float* gnn_bnvb = (const float*)d_in[27];
    const float* gnn_bnew = (const float*)d_in[28];
    const float* gnn_bneb = (const float*)d_in[29];
    const float* main_sc = (const float*)d_in[30];
    const float* sub_sc  = (const float*)d_in[31];
    float* out = (float*)d_out;

    float* S = nullptr;
    cudaGetSymbolAddress((void**)&S, g_scratch);
    int* pairs = nullptr;
    cudaGetSymbolAddress((void**)&pairs, g_pairs);

    size_t off = 0;
    auto take = [&](size_t n) { float* p = S + off; off += (n + 3) & ~(size_t)3; return p; };
    float* tmp_   = take((size_t)NN_ * BD * CC);
    float* fu_    = take((size_t)BB * NN_ * DD * CC);
    float* feat_  = take((size_t)BB * ND * CC);
    float* VP_    = take((size_t)BB * ND * CC);
    float* q_     = take((size_t)BB * ND * C2);
    float* QK_    = take((size_t)BB * ND * CC);      // [MR, 512]: Q = cols 0..255, K = 256..511
    float* dots_  = take((size_t)BB * ND * ND);
    float* fe_    = take((size_t)BB * NE * CC);
    float* el_    = take((size_t)BB * NE * CC);
    float* attnp_ = take((size_t)BB * ND * 64);      // padded attention
    float* MMT_   = take((size_t)BB * NN_ * DD * DD);
    float* kb_    = take((size_t)BB * DD * C2);
    float* vbp_   = take((size_t)BB * 64 * CC);      // padded V
    float* fv_    = take((size_t)BB * NN_ * CC);
    float* W2_    = take((size_t)CC * CC);
    float* Wqk_   = take((size_t)CC * CC);           // [512,512]: rows 0..255 qW, 256..511 kW
    float* qkb_   = take(CC);
    float* Wcat_  = take((size_t)2 * 4 * CC * CC);   // per-layer [2048, 512]
    float* vcat_  = take((size_t)BB * NN_ * VLD);    // [108, 2048]: vi|vj|ui|uj
    float* csbuf_ = take((size_t)BB * NN_ * NN_ * 64);
    float* nmean_ = take(NN_ * CC);
    float* nrstd_ = take(NN_ * CC);
    float* Ms_    = take(MR);
    float* Mb_    = take(MR);
    float* part1_ = take(BB * NE);
    float* part2_ = take(BB * NE);
    float* esc_   = take(NE);
    float* esh_   = take(NE);
    float* agg_   = take((size_t)BB * NN_ * CC);
    float* bias2_ = take(CC);
    float* misc_  = take(2);
    float* emsc_  = take(NE);
    float* emsh_  = take(NE);
    float* nvsc_  = take(NN_);
    float* nvsh_  = take(NN_);

    const size_t WSZ = (size_t)CC * CC;

    auto f2_nt = [](const float* A, int lda, size_t sA, const float* Bm, int ldb, size_t sB,
                    float* Cc, int ldc, size_t sC, const float* bias, size_t sBias,
                    int M, int Nn, int K, int batch, float alpha) {
        dim3 g((Nn + 127) / 128, (M + 127) / 128, batch);
        gemm_f2<true><<<g, 256>>>(A, lda, sA, Bm, ldb, sB, Cc, ldc, sC, bias, sBias, M, Nn, K, alpha);
    };
    auto f2_nn = [](const float* A, int lda, size_t sA, const float* Bm, int ldb, size_t sB,
                    float* Cc, int ldc, size_t sC, const float* bias, size_t sBias,
                    int M, int Nn, int K, int batch, float alpha) {
        dim3 g((Nn + 127) / 128, (M + 127) / 128, batch);
        gemm_f2<false><<<g, 256>>>(A, lda, sA, Bm, ldb, sB, Cc, ldc, sC, bias, sBias, M, Nn, K, alpha);
    };
    auto small_nt = [](const float* A, int lda, size_t sA, const float* Bm, int ldb, size_t sB,
                       float* Cc, int ldc, size_t sC, const float* bias, size_t sBias,
                       int M, int Nn, int K, int batch, float alpha) {
        dim3 g((Nn + 31) / 32, (M + 31) / 32, batch);
        gemm_small<true, 0><<<g, 256>>>(A, lda, sA, Bm, ldb, sB, Cc, ldc, sC, bias, sBias,
                                        M, Nn, K, alpha, nullptr, nullptr);
    };
    auto small_nn = [](const float* A, int lda, size_t sA, const float* Bm, int ldb, size_t sB,
                       float* Cc, int ldc, size_t sC, const float* bias, size_t sBias,
                       int M, int Nn, int K, int batch, float alpha) {
        dim3 g((Nn + 31) / 32, (M + 31) / 32, batch);
        gemm_small<false, 0><<<g, 256>>>(A, lda, sA, Bm, ldb, sB, Cc, ldc, sC, bias, sBias,
                                         M, Nn, K, alpha, nullptr, nullptr);
    };

    pair_init_kernel<<<(NPAIR + 255) / 256, 256>>>(pairs);

    // ---- weight concats (D2D copies; graph-capturable) ----
    cudaMemcpyAsync(Wqk_, arm_qW, (size_t)C2 * CC * 4, cudaMemcpyDeviceToDevice);
    cudaMemcpyAsync(Wqk_ + (size_t)C2 * CC, arm_kW, (size_t)C2 * CC * 4, cudaMemcpyDeviceToDevice);
    cudaMemcpyAsync(qkb_, arm_qb, C2 * 4, cudaMemcpyDeviceToDevice);
    cudaMemcpyAsync(qkb_ + C2, arm_kb, C2 * 4, cudaMemcpyDeviceToDevice);
    for (int l = 0; l < 2; l++) {
        float* W = Wcat_ + (size_t)l * 4 * WSZ;
        cudaMemcpyAsync(W + 0 * WSZ, gnn_aW + (size_t)l * WSZ, WSZ * 4, cudaMemcpyDeviceToDevice);
        cudaMemcpyAsync(W + 1 * WSZ, gnn_bW + (size_t)l * WSZ, WSZ * 4, cudaMemcpyDeviceToDevice);
        cudaMemcpyAsync(W + 2 * WSZ, gnn_uW + (size_t)l * WSZ, WSZ * 4, cudaMemcpyDeviceToDevice);
        cudaMemcpyAsync(W + 3 * WSZ, gnn_vW + (size_t)l * WSZ, WSZ * 4, cudaMemcpyDeviceToDevice);
    }

    // ---- precompute W2 = ep_W @ arm_vW, bias2 = ep_W @ arm_vb, ep_b sums ----
    small_nn(ep_W, CC, 0, arm_vW, CC, 0, W2_, CC, 0, nullptr, 0, CC, CC, CC, 1, 1.f);
    misc_kernel<<<1, 512>>>(ep_W, arm_vb, ep_b, bias2_, misc_);

    // ---- node blocks ----
    f2_nt(x, CC, 0, nb_W, CC, WSZ, tmp_, CC, (size_t)BD * CC, nb_b, CC,
          BD, CC, CC, NN_, 1.f);
    bnstat_node_kernel<<<(NN_ * CC + 255) / 256, 256>>>(tmp_, nmean_, nrstd_);
    node_apply_fused<<<(BB * NN_ * CC + 255) / 256, 256>>>(tmp_, nmean_, nrstd_,
                                                           nb_bnw, nb_bnb, fu_, fv_);

    // ---- FAM cross attention ----
    small_nt(x, CC, 0, fam_kW, CC, 0, kb_, C2, 0, fam_kb, 0, BD, C2, CC, 1, 1.f);
    // V padded to [BB][64][512] (rows 49..63 zeroed)
    small_nt(x, CC, (size_t)DD * CC, fam_vW, CC, 0, vbp_, CC, (size_t)64 * CC, fam_vb, 0,
             DD, CC, CC, BB, 1.f);
    vbp_zero_kernel<<<(BB * 15 * CC + 255) / 256, 256>>>(vbp_);
    {   // q = fu @ fam_qW^T (old fast kernel, N=256)
        dim3 g((C2 + 63) / 64, (MR + 127) / 128, 1);
        gemm_fast<true, 0><<<g, 256>>>(fu_, 0, fam_qW, 0, q_, 0, fam_qb, 0,
                                       MR, C2, CC, 1.f, nullptr, nullptr, 0);
    }
    small_nt(q_, C2, (size_t)ND * C2, kb_, C2, (size_t)DD * C2, attnp_, 64, (size_t)ND * 64,
             nullptr, 0, ND, DD, C2, BB, SCALE);
    softmax49_kernel<<<(MR + 7) / 8, 256>>>(attnp_, MR);
    // feat = attn_p @ vb_p  (K=64 fast path)
    f2_nn(attnp_, 64, (size_t)ND * 64, vbp_, CC, (size_t)64 * CC, feat_, CC, (size_t)ND * CC,
          nullptr, 0, ND, CC, 64, BB, 1.f);

    // ---- ARM projections: QK fused, VP (V folded with ep_W) ----
    f2_nt(feat_, CC, 0, Wqk_, CC, 0, QK_, CC, 0, qkb_, 0, MR, CC, CC, 1, 1.f);
    f2_nt(feat_, CC, 0, W2_, CC, 0, VP_, CC, 0, bias2_, 0, MR, CC, CC, 1, 1.f);

    // ---- pairwise dots: Q @ K^T, Q/K are column halves of QK_ ----
    f2_nt(QK_, CC, (size_t)ND * CC, QK_ + C2, CC, (size_t)ND * CC, dots_, ND, (size_t)ND * ND,
          nullptr, 0, ND, ND, C2, BB, SCALE);

    // ---- per-(b,i): M M^T (upper), row sums, M@ep_b ----
    mmt_kernel<<<BB * NN_, 256>>>(VP_, pairs, MMT_);
    msmb_kernel<<<(MR + 7) / 8, 256>>>(VP_, ep_b, Ms_, Mb_);

    // ---- per-edge: softmax + BN-stat partials; export colsum/D (padded 64) ----
    {
        dim3 g(NE, BB);
        edge_kernel<<<g, 256>>>(dots_, MMT_, Ms_, Mb_, misc_, pairs, part1_, part2_, csbuf_);
    }
    edge_finalize_kernel<<<(NE + 255) / 256, 256>>>(part1_, part2_, gem_bnw, gem_bnb, esc_, esh_);
    // fe[b, i*27+j, :] = BN affine applied in epilogue: ((cs/D)@VP + ep_b)*esc + esh
    {
        dim3 g((CC + 31) / 32, (NN_ + 31) / 32, BB * NN_);
        gemm_small<false, 2><<<g, 256>>>(csbuf_, 64, (size_t)NN_ * 64, VP_, CC, (size_t)DD * CC,
                                         fe_, CC, (size_t)NN_ * CC, ep_b, 0,
                                         NN_, CC, DD, 1.f, esc_, esh_);
    }

    // ---- 2 GatedGNN layers ----
    for (int l = 0; l < 2; l++) {
        const float* eW = gnn_eW + (size_t)l * WSZ;
        const float* Wc = Wcat_ + (size_t)l * 4 * WSZ;
        float* vi_ = vcat_ + 0;
        float* vj_ = vcat_ + 512;
        float* ui_ = vcat_ + 1024;
        float* uj_ = vcat_ + 1536;
        // vcat = fv @ [aW;bW;uW;vW]^T  -> [108, 2048]
        small_nt(fv_, CC, 0, Wc, CC, 0, vcat_, VLD, 0, nullptr, 0,
                 BB * NN_, 4 * CC, CC, 1, 1.f);
        // el = fe @ eW^T + vi[b,i] + vj[b,j]
        {
            dim3 g((CC + 63) / 64, (BB * NE + 127) / 128, 1);
            gemm_fast<true, 1><<<g, 256>>>(fe_, 0, eW, 0, el_, 0, nullptr, 0,
                                           BB * NE, CC, CC, 1.f, vi_, vj_, VLD);
        }
        int tot = BB * NE * CC;
        bnstat_bc_kernel<<<NE, 256>>>(el_, NE, gnn_bnew + (size_t)l * NE, gnn_bneb + (size_t)l * NE,
                                      emsc_, emsh_);
        fe_update_kernel<<<(tot + 255) / 256, 256>>>(fe_, el_, emsc_, emsh_);
        agg_kernel<<<(BB * NN_ * CC + 255) / 256, 256>>>(fe_, ui_, uj_, agg_);
        bnstat_bc_kernel<<<NN_, 256>>>(agg_, NN_, gnn_bnvw + (size_t)l * NN_,
                                       gnn_bnvb + (size_t)l * NN_, nvsc_, nvsh_);
        fv_update_kernel<<<(BB * NN_ * CC + 255) / 256, 256>>>(fv_, agg_, nvsc_, nvsh_);
    }

    // ---- SC cosine outputs ----
    {
        dim3 g(41, BB);
        sc_kernel<<<g, 128>>>(fv_, main_sc, sub_sc, out);
    }
}

// round 11
// speedup vs baseline: 1.5518x; 1.0849x over previous
#include <cuda_runtime.h>
#include <math.h>

#define BB 4
#define DD 49
#define CC 512
#define C2 256
#define NN_ 27
#define NE 729      // N*N
#define ND 1323     // N*D
#define BD 196      // B*D
#define MR 5292     // B*N*D
#define NPAIR 1225  // DD*(DD+1)/2
#define VLD 2048    // stride of concatenated GNN node projections
#define BN_EPS 1e-5f
#define SCALE 0.0625f   // 256^-0.5

__device__ float g_scratch[33000000];
__device__ int g_pairs[NPAIR];

__constant__ int c_subidx[14] = {0,0,1,1,2,2,4,4,7,7,8,8,11,11};

// ---------------- utilities ----------------
__device__ __forceinline__ float blockReduceSum(float v, float* sh) {
    __syncthreads();
    int lane = threadIdx.x & 31, w = threadIdx.x >> 5;
#pragma unroll
    for (int o = 16; o; o >>= 1) v += __shfl_xor_sync(0xffffffffu, v, o);
    if (lane == 0) sh[w] = v;
    __syncthreads();
    float r = 0.f;
    if (w == 0) {
        int nw = (blockDim.x + 31) >> 5;
        r = (lane < nw) ? sh[lane] : 0.f;
#pragma unroll
        for (int o = 16; o; o >>= 1) r += __shfl_xor_sync(0xffffffffu, r, o);
    }
    return r;
}

// =============== gemm_f2: 128x128x16 tile, 256 thr, 8x8/thread, K%16==0 ===============
// Conflict-free split-fragment microkernel: each thread owns rows {ty*4..+3, 64+ty*4..+3}
// and cols {tx*4..+3, 64+tx*4..+3}.
// TRANSB=true : B is [N,K] row-major with leading dim ldb; C = alpha*A@B^T + bias
// TRANSB=false: B is [K,N] row-major with leading dim ldb; C = alpha*A@B + bias
template<bool TRANSB>
__global__ void __launch_bounds__(256, 2)
gemm_f2(const float* __restrict__ A, int lda, size_t sA,
        const float* __restrict__ Bm, int ldb, size_t sB,
        float* __restrict__ Cm, int ldc, size_t sC,
        const float* __restrict__ bias, size_t sBias,
        int M, int Nn, int K, float alpha)
{
    const int BK = 16;
    const int LDS = 132;   // padded row: 132*4B = 528B, 16B-aligned, kills STS conflicts
    int bz = blockIdx.z;
    A  += (size_t)bz * sA;
    Bm += (size_t)bz * sB;
    Cm += (size_t)bz * sC;
    int m0 = blockIdx.y * 128, n0 = blockIdx.x * 128;

    __shared__ float As[BK][LDS];
    __shared__ float Bs[BK][LDS];

    int tid = threadIdx.x;
    int tx = tid & 15, ty = tid >> 4;

    // A: thread loads 2 float4 along K for one m-row
    int am = tid >> 1, akq = (tid & 1) << 3;
    bool aok = (m0 + am) < M;
    const float* Ap = A + (size_t)(m0 + am) * lda + akq;

    // B mappings
    int bn = tid >> 1, bkq = (tid & 1) << 3;          // TRANSB
    int nk0 = tid >> 5, nq0 = (tid & 31) << 2;        // NN: elem 0 (k rows 0..7)
    int nk1 = nk0 + 8;                                // NN: elem 1 (k rows 8..15)
    const float* Bp;
    bool bok;
    if (TRANSB) {
        bok = (n0 + bn) < Nn;
        Bp = Bm + (size_t)(n0 + bn) * ldb + bkq;
    } else {
        bok = (n0 + nq0 + 3) < Nn;
        Bp = Bm + n0 + nq0;
    }
    const float4 z4 = make_float4(0.f, 0.f, 0.f, 0.f);

    float acc[8][8];
#pragma unroll
    for (int i = 0; i < 8; i++)
#pragma unroll
        for (int j = 0; j < 8; j++) acc[i][j] = 0.f;

    auto ldA = [&](int k0, float4& x, float4& y) {
        if (aok) { x = *(const float4*)(Ap + k0); y = *(const float4*)(Ap + k0 + 4); }
        else { x = z4; y = z4; }
    };
    auto ldB = [&](int k0, float4& x, float4& y) {
        if (TRANSB) {
            if (bok) { x = *(const float4*)(Bp + k0); y = *(const float4*)(Bp + k0 + 4); }
            else { x = z4; y = z4; }
        } else {
            const float* r0 = Bp + (size_t)(k0 + nk0) * ldb;
            const float* r1 = Bp + (size_t)(k0 + nk1) * ldb;
            if (bok) { x = *(const float4*)r0; y = *(const float4*)r1; }
            else {
                x = z4; y = z4;
                int gn = n0 + nq0;
                if (gn < Nn)     { x.x = r0[0]; y.x = r1[0]; }
                if (gn + 1 < Nn) { x.y = r0[1]; y.y = r1[1]; }
                if (gn + 2 < Nn) { x.z = r0[2]; y.z = r1[2]; }
            }
        }
    };
    auto stAB = [&](float4 ax, float4 ay, float4 bx, float4 by) {
        As[akq + 0][am] = ax.x; As[akq + 1][am] = ax.y;
        As[akq + 2][am] = ax.z; As[akq + 3][am] = ax.w;
        As[akq + 4][am] = ay.x; As[akq + 5][am] = ay.y;
        As[akq + 6][am] = ay.z; As[akq + 7][am] = ay.w;
        if (TRANSB) {
            Bs[bkq + 0][bn] = bx.x; Bs[bkq + 1][bn] = bx.y;
            Bs[bkq + 2][bn] = bx.z; Bs[bkq + 3][bn] = bx.w;
            Bs[bkq + 4][bn] = by.x; Bs[bkq + 5][bn] = by.y;
            Bs[bkq + 6][bn] = by.z; Bs[bkq + 7][bn] = by.w;
        } else {
            *(float4*)&Bs[nk0][nq0] = bx;
            *(float4*)&Bs[nk1][nq0] = by;
        }
    };

    int KT = K >> 4;
    {
        float4 ax, ay, bx, by;
        ldA(0, ax, ay); ldB(0, bx, by);
        stAB(ax, ay, bx, by);
    }
    __syncthreads();

    for (int kt = 0; kt < KT; kt++) {
        float4 nax, nay, nbx, nby;
        bool more = (kt + 1) < KT;
        if (more) {
            int k0 = (kt + 1) << 4;
            ldA(k0, nax, nay); ldB(k0, nbx, nby);
        }
#pragma unroll
        for (int kk = 0; kk < BK; kk++) {
            float4 a0 = *(const float4*)&As[kk][ty << 2];
            float4 a1 = *(const float4*)&As[kk][64 + (ty << 2)];
            float4 b0 = *(const float4*)&Bs[kk][tx << 2];
            float4 b1 = *(const float4*)&Bs[kk][64 + (tx << 2)];
            float a[8] = {a0.x, a0.y, a0.z, a0.w, a1.x, a1.y, a1.z, a1.w};
            float b[8] = {b0.x, b0.y, b0.z, b0.w, b1.x, b1.y, b1.z, b1.w};
#pragma unroll
            for (int i = 0; i < 8; i++)
#pragma unroll
                for (int j = 0; j < 8; j++)
                    acc[i][j] += a[i] * b[j];
        }
        __syncthreads();
        if (more) { stAB(nax, nay, nbx, nby); }
        __syncthreads();
    }

    const float* bp = bias ? (bias + (size_t)bz * sBias) : nullptr;
    bool ldc4 = ((ldc & 3) == 0);
#pragma unroll
    for (int g = 0; g < 2; g++) {
#pragma unroll
        for (int i = 0; i < 4; i++) {
            int gm = m0 + g * 64 + (ty << 2) + i;
            if (gm >= M) continue;
            float* crow = Cm + (size_t)gm * ldc;
            int ii = g * 4 + i;
#pragma unroll
            for (int h = 0; h < 2; h++) {
                int gn = n0 + h * 64 + (tx << 2);
                if (gn >= Nn) continue;
                int jj = h * 4;
                float4 v;
                v.x = acc[ii][jj + 0] * alpha;
                v.y = acc[ii][jj + 1] * alpha;
                v.z = acc[ii][jj + 2] * alpha;
                v.w = acc[ii][jj + 3] * alpha;
                if (bp) {
                    if (gn + 3 < Nn) {
                        float4 bv = *(const float4*)&bp[gn];
                        v.x += bv.x; v.y += bv.y; v.z += bv.z; v.w += bv.w;
                    } else {
                        v.x += bp[gn];
                        if (gn + 1 < Nn) v.y += bp[gn + 1];
                        if (gn + 2 < Nn) v.z += bp[gn + 2];
                    }
                }
                if (ldc4 && gn + 3 < Nn) {
                    *(float4*)&crow[gn] = v;
                } else {
                    crow[gn] = v.x;
                    if (gn + 1 < Nn) crow[gn + 1] = v.y;
                    if (gn + 2 < Nn) crow[gn + 2] = v.z;
                    if (gn + 3 < Nn) crow[gn + 3] = v.w;
                }
            }
        }
    }
}

// =============== old fast GEMM: 128x64, 8x4/thread (conflict-free; N=256/EPI paths) ===
// EPI==1: epilogue adds evi[(b,i),c] + evj[(b,j),c] with stride evld.
template<bool TRANSB, int EPI>
__global__ void __launch_bounds__(256, 2)
gemm_fast(const float* __restrict__ A, size_t sA,
          const float* __restrict__ Bm, size_t sB,
          float* __restrict__ Cm, size_t sC,
          const float* __restrict__ bias, size_t sBias,
          int M, int Nn, int K, float alpha,
          const float* __restrict__ evi, const float* __restrict__ evj, int evld)
{
    const int BK = 16;
    int bz = blockIdx.z;
    A  += (size_t)bz * sA;
    Bm += (size_t)bz * sB;
    Cm += (size_t)bz * sC;
    int m0 = blockIdx.y * 128, n0 = blockIdx.x * 64;

    __shared__ float As[BK][128];
    __shared__ float Bs[BK][64];

    int tid = threadIdx.x;
    int tx = tid & 15, ty = tid >> 4;

    int ar0 = tid >> 2;
    int ar1 = ar0 + 64;
    int ak  = (tid & 3) << 2;
    int gm0 = m0 + ar0, gm1 = m0 + ar1;
    bool a0ok = gm0 < M, a1ok = gm1 < M;
    const float* Arow0 = A + (size_t)gm0 * K + ak;
    const float* Arow1 = A + (size_t)gm1 * K + ak;

    int bn = tid >> 2, bkq = (tid & 3) << 2;
    bool bok = (n0 + bn) < Nn;
    const float* Bptr = Bm + (size_t)(n0 + bn) * K + bkq;

    const float4 z4 = make_float4(0.f, 0.f, 0.f, 0.f);

    float acc[8][4];
#pragma unroll
    for (int i = 0; i < 8; i++)
#pragma unroll
        for (int j = 0; j < 4; j++) acc[i][j] = 0.f;

    auto store = [&](float4 a0, float4 a1, float4 b) {
        As[ak + 0][ar0] = a0.x; As[ak + 1][ar0] = a0.y;
        As[ak + 2][ar0] = a0.z; As[ak + 3][ar0] = a0.w;
        As[ak + 0][ar1] = a1.x; As[ak + 1][ar1] = a1.y;
        As[ak + 2][ar1] = a1.z; As[ak + 3][ar1] = a1.w;
        Bs[bkq + 0][bn] = b.x; Bs[bkq + 1][bn] = b.y;
        Bs[bkq + 2][bn] = b.z; Bs[bkq + 3][bn] = b.w;
    };

    int KT = K >> 4;
    {
        float4 pa0 = a0ok ? *(const float4*)Arow0 : z4;
        float4 pa1 = a1ok ? *(const float4*)Arow1 : z4;
        float4 pb  = bok ? *(const float4*)Bptr : z4;
        store(pa0, pa1, pb);
    }
    __syncthreads();

    for (int kt = 0; kt < KT; kt++) {
        float4 na0, na1, nb;
        bool more = (kt + 1) < KT;
        if (more) {
            int k0 = (kt + 1) << 4;
            na0 = a0ok ? *(const float4*)(Arow0 + k0) : z4;
            na1 = a1ok ? *(const float4*)(Arow1 + k0) : z4;
            nb  = bok ? *(const float4*)(Bptr + k0) : z4;
        }
#pragma unroll
        for (int kk = 0; kk < BK; kk++) {
            float4 b4 = *(const float4*)&Bs[kk][tx << 2];
            float4 aA = *(const float4*)&As[kk][ty << 3];
            float4 aB = *(const float4*)&As[kk][(ty << 3) + 4];
            float a[8] = {aA.x, aA.y, aA.z, aA.w, aB.x, aB.y, aB.z, aB.w};
            float bv[4] = {b4.x, b4.y, b4.z, b4.w};
#pragma unroll
            for (int i = 0; i < 8; i++)
#pragma unroll
                for (int j = 0; j < 4; j++)
                    acc[i][j] += a[i] * bv[j];
        }
        __syncthreads();
        if (more) store(na0, na1, nb);
        __syncthreads();
    }

    const float* bp = bias ? (bias + (size_t)bz * sBias) : nullptr;
    bool nn4 = ((Nn & 3) == 0);
#pragma unroll
    for (int i = 0; i < 8; i++) {
        int gm = m0 + (ty << 3) + i;
        if (gm >= M) continue;
        float* crow = Cm + (size_t)gm * Nn;
        const float* vip = nullptr; const float* vjp = nullptr;
        if (EPI == 1) {
            int b = gm / NE; int e = gm - b * NE;
            int ii = e / NN_; int jj = e - ii * NN_;
            vip = evi + (size_t)(b * NN_ + ii) * evld;
            vjp = evj + (size_t)(b * NN_ + jj) * evld;
        }
        int gn = n0 + (tx << 2);
        if (nn4 && gn + 3 < Nn) {
            float4 v;
            v.x = acc[i][0] * alpha; v.y = acc[i][1] * alpha;
            v.z = acc[i][2] * alpha; v.w = acc[i][3] * alpha;
            if (bp) {
                float4 bv = *(const float4*)&bp[gn];
                v.x += bv.x; v.y += bv.y; v.z += bv.z; v.w += bv.w;
            }
            if (EPI == 1) {
                float4 vi4 = *(const float4*)&vip[gn];
                float4 vj4 = *(const float4*)&vjp[gn];
                v.x += vi4.x + vj4.x; v.y += vi4.y + vj4.y;
                v.z += vi4.z + vj4.z; v.w += vi4.w + vj4.w;
            }
            *(float4*)&crow[gn] = v;
        } else {
#pragma unroll
            for (int j = 0; j < 4; j++) {
                int g2 = gn + j;
                if (g2 >= Nn) continue;
                float v = acc[i][j] * alpha;
                if (bp) v += bp[g2];
                if (EPI == 1) v += vip[g2] + vjp[g2];
                crow[g2] = v;
            }
        }
    }
}

// =============== SMALL tiled GEMM (any K): 32x32 tile, 2x2/thread, with ld params =====
// EPI==2: v = (acc*alpha + bias) * esc[e] + esh[e],  e = (bz%NN_)*NN_ + gm
template<bool TRANSB, int EPI>
__global__ void gemm_small(const float* __restrict__ A, int lda, size_t sA,
                           const float* __restrict__ Bm, int ldb, size_t sB,
                           float* __restrict__ Cm, int ldc, size_t sC,
                           const float* __restrict__ bias, size_t sBias,
                           int M, int Nn, int K, float alpha,
                           const float* __restrict__ esc, const float* __restrict__ esh)
{
    const int BK = 16;
    int bz = blockIdx.z;
    A  += (size_t)bz * sA;
    Bm += (size_t)bz * sB;
    Cm += (size_t)bz * sC;
    int m0 = blockIdx.y * 32, n0 = blockIdx.x * 32;

    __shared__ float As[BK][33];
    __shared__ float Bs[BK][33];

    int tid = threadIdx.x;
    int ty = tid >> 4, tx = tid & 15;
    float acc[2][2] = {};

    for (int k0 = 0; k0 < K; k0 += BK) {
#pragma unroll
        for (int t = 0; t < 2; t++) {
            int e = tid + t * 256;
            int m = e >> 4, k = e & 15;
            float v = 0.f;
            int gm = m0 + m, gk = k0 + k;
            if (gm < M && gk < K) v = A[(size_t)gm * lda + gk];
            As[k][m] = v;
        }
#pragma unroll
        for (int t = 0; t < 2; t++) {
            int e = tid + t * 256;
            float v = 0.f;
            if (TRANSB) {
                int n = e >> 4, k = e & 15;
                int gn = n0 + n, gk = k0 + k;
                if (gn < Nn && gk < K) v = Bm[(size_t)gn * ldb + gk];
                Bs[k][n] = v;
            } else {
                int k = e >> 5, n = e & 31;
                int gk = k0 + k, gn = n0 + n;
                if (gk < K && gn < Nn) v = Bm[(size_t)gk * ldb + gn];
                Bs[k][n] = v;
            }
        }
        __syncthreads();
#pragma unroll
        for (int kk = 0; kk < BK; kk++) {
            float a0 = As[kk][2 * ty], a1 = As[kk][2 * ty + 1];
            float b0 = Bs[kk][2 * tx], b1 = Bs[kk][2 * tx + 1];
            acc[0][0] += a0 * b0; acc[0][1] += a0 * b1;
            acc[1][0] += a1 * b0; acc[1][1] += a1 * b1;
        }
        __syncthreads();
    }

    const float* bp = bias ? (bias + (size_t)bz * sBias) : nullptr;
#pragma unroll
    for (int i = 0; i < 2; i++) {
        int gm = m0 + 2 * ty + i;
        if (gm >= M) continue;
#pragma unroll
        for (int j = 0; j < 2; j++) {
            int gn = n0 + 2 * tx + j;
            if (gn >= Nn) continue;
            float v = acc[i][j] * alpha;
            if (bp) v += bp[gn];
            if (EPI == 2) {
                int i_ = bz % NN_;
                int e = i_ * NN_ + gm;
                v = v * esc[e] + esh[e];
            }
            Cm[(size_t)gm * ldc + gn] = v;
        }
    }
}

// ---------------- pair table for symmetric trace ----------------
__global__ void pair_init_kernel(int* pairs)
{
    int t = blockIdx.x * blockDim.x + threadIdx.x;
    if (t >= NPAIR) return;
    int p = 0, base = 0;
    while (base + (DD - p) <= t) { base += DD - p; p++; }
    int q = p + (t - base);
    pairs[t] = (p << 8) | q;
}

// ---------------- dedicated MMT gram kernel: per-(b,i), upper triangle only ----------
__global__ void mmt_kernel(const float* __restrict__ VP, const int* __restrict__ pairs,
                           float* __restrict__ MMT)
{
    int bi = blockIdx.x;  // b*NN_+i
    const float* Mp = VP + (size_t)bi * DD * CC;
    __shared__ float sh[DD][36];
    int tid = threadIdx.x;

    int pp[5], qq[5];
    float4 acc[5];
#pragma unroll
    for (int s = 0; s < 5; s++) {
        int t = tid + s * 256;
        acc[s] = make_float4(0.f, 0.f, 0.f, 0.f);
        if (t < NPAIR) { int pq = pairs[t]; pp[s] = pq >> 8; qq[s] = pq & 255; }
        else { pp[s] = -1; qq[s] = 0; }
    }

    for (int k0 = 0; k0 < CC; k0 += 32) {
        __syncthreads();
        for (int e = tid; e < DD * 8; e += 256) {
            int r = e >> 3, kq = (e & 7) << 2;
            *(float4*)&sh[r][kq] = *(const float4*)(Mp + (size_t)r * CC + k0 + kq);
        }
        __syncthreads();
#pragma unroll
        for (int s = 0; s < 5; s++) {
            if (pp[s] < 0) continue;
            const float* rp = sh[pp[s]];
            const float* rq = sh[qq[s]];
#pragma unroll
            for (int kk = 0; kk < 32; kk += 4) {
                float4 a = *(const float4*)(rp + kk);
                float4 b = *(const float4*)(rq + kk);
                acc[s].x += a.x * b.x; acc[s].y += a.y * b.y;
                acc[s].z += a.z * b.z; acc[s].w += a.w * b.w;
            }
        }
    }
#pragma unroll
    for (int s = 0; s < 5; s++) {
        if (pp[s] < 0) continue;
        float r = (acc[s].x + acc[s].y) + (acc[s].z + acc[s].w);
        MMT[(size_t)bi * DD * DD + pp[s] * DD + qq[s]] = r;
    }
}

// ---------------- misc precompute ----------------
__global__ void misc_kernel(const float* __restrict__ epW, const float* __restrict__ armvb,
                            const float* __restrict__ epb, float* bias2, float* misc)
{
    int t = threadIdx.x;  // 512
    float s = 0.f;
    for (int c = 0; c < CC; c++) s += epW[(size_t)t * CC + c] * armvb[c];
    bias2[t] = s;
    __shared__ float red[32];
    float v = epb[t];
    float s1 = blockReduceSum(v, red);
    float s2 = blockReduceSum(v * v, red);
    if (t == 0) { misc[0] = s1; misc[1] = s2; }
}

// ---------------- node BN stats over (B,D) per (n,c) ----------------
__global__ void bnstat_node_kernel(const float* __restrict__ tmp, float* mean, float* rstd)
{
    int idx = blockIdx.x * blockDim.x + threadIdx.x;
    if (idx >= NN_ * CC) return;
    int n = idx >> 9, c = idx & 511;
    const float* p = tmp + (size_t)n * BD * CC + c;
    float s = 0.f, sq = 0.f;
    for (int r = 0; r < BD; r++) { float v = p[(size_t)r * CC]; s += v; sq += v * v; }
    float m = s / (float)BD;
    mean[idx] = m;
    rstd[idx] = rsqrtf(sq / (float)BD - m * m + BN_EPS);
}

// ---------------- fused: f_u = relu(BN(tmp)) + GAP -> f_v ----------------
__global__ void node_apply_fused(const float* __restrict__ tmp, const float* __restrict__ mean,
                                 const float* __restrict__ rstd, const float* __restrict__ w,
                                 const float* __restrict__ bb,
                                 float* __restrict__ fu, float* __restrict__ fv)
{
    int idx = blockIdx.x * blockDim.x + threadIdx.x;
    if (idx >= BB * NN_ * CC) return;
    int c = idx & 511;
    int n = (idx >> 9) % NN_;
    int b = idx / (NN_ * CC);
    int nc = (n << 9) + c;
    float mu = mean[nc], rs = rstd[nc] * w[nc], bias = bb[nc];
    const float* tp = tmp + ((size_t)n * BD + b * DD) * CC + c;
    float* fp = fu + ((size_t)(b * NN_ + n) * DD) * CC + c;
    float s = 0.f;
    for (int d = 0; d < DD; d++) {
        float v = fmaxf((tp[(size_t)d * CC] - mu) * rs + bias, 0.f);
        fp[(size_t)d * CC] = v;
        s += v;
    }
    fv[idx] = s * (1.f / (float)DD);
}

// ---------------- zero pad rows 49..63 of vb_p ----------------
__global__ void vbp_zero_kernel(float* __restrict__ vbp)
{
    int idx = blockIdx.x * blockDim.x + threadIdx.x;
    if (idx >= BB * 15 * CC) return;
    int c = idx % CC;
    int r = (idx / CC) % 15;
    int b = idx / (15 * CC);
    vbp[((size_t)b * 64 + 49 + r) * CC + c] = 0.f;
}

// ---------------- softmax over padded rows [*,64], cols 49..63 zeroed ----------------
__global__ void softmax49_kernel(float* __restrict__ data, int rows)
{
    int row = blockIdx.x * 8 + (threadIdx.x >> 5);
    if (row >= rows) return;
    int lane = threadIdx.x & 31;
    float* p = data + (size_t)row * 64;
    float v0 = p[lane];
    float v1 = (lane + 32 < DD) ? p[lane + 32] : -3.4e38f;
    float mx = fmaxf(v0, v1);
#pragma unroll
    for (int o = 16; o; o >>= 1) mx = fmaxf(mx, __shfl_xor_sync(0xffffffffu, mx, o));
    float e0 = __expf(v0 - mx);
    float e1 = (lane + 32 < DD) ? __expf(v1 - mx) : 0.f;
    float s = e0 + e1;
#pragma unroll
    for (int o = 16; o; o >>= 1) s += __shfl_xor_sync(0xffffffffu, s, o);
    float inv = 1.f / s;
    p[lane] = e0 * inv;
    p[lane + 32] = (lane + 32 < DD) ? e1 * inv : 0.f;
}

// ---------------- Ms (row sums) and Mb (rows @ ep_b) of VP ----------------
__global__ void msmb_kernel(const float* __restrict__ VP, const float* __restrict__ epb,
                            float* __restrict__ Ms, float* __restrict__ Mb)
{
    int row = blockIdx.x * 8 + (threadIdx.x >> 5);
    if (row >= MR) return;
    int lane = threadIdx.x & 31;
    const float* p = VP + (size_t)row * CC;
    float s = 0.f, sb = 0.f;
    for (int c = lane; c < CC; c += 32) { float v = p[c]; s += v; sb += v * epb[c]; }
#pragma unroll
    for (int o = 16; o; o >>= 1) {
        s  += __shfl_xor_sync(0xffffffffu, s, o);
        sb += __shfl_xor_sync(0xffffffffu, sb, o);
    }
    if (lane == 0) { Ms[row] = s; Mb[row] = sb; }
}

// ---------------- per-edge kernel: softmax + BN-stat partials + colsum export --------
__global__ void edge_kernel(const float* __restrict__ dots, const float* __restrict__ MMT,
                            const float* __restrict__ Ms, const float* __restrict__ Mb,
                            const float* __restrict__ misc, const int* __restrict__ pairs,
                            float* __restrict__ part1, float* __restrict__ part2,
                            float* __restrict__ csbuf)
{
    int e = blockIdx.x, b = blockIdx.y;
    int i = e / NN_, j = e % NN_;
    __shared__ float A[DD][52];
    __shared__ float cs[DD];
    __shared__ float red[32];
    int tid = threadIdx.x, lane = tid & 31, w = tid >> 5;

    const float* P = dots + (size_t)b * ND * ND + (size_t)(j * DD) * ND + i * DD;
    for (int d = w; d < DD; d += 8) {
        const float* pr = P + (size_t)d * ND;
        float v0 = pr[lane];
        float v1 = (lane + 32 < DD) ? pr[lane + 32] : -3.4e38f;
        float mx = fmaxf(v0, v1);
#pragma unroll
        for (int o = 16; o; o >>= 1) mx = fmaxf(mx, __shfl_xor_sync(0xffffffffu, mx, o));
        float e0 = __expf(v0 - mx);
        float e1 = (lane + 32 < DD) ? __expf(v1 - mx) : 0.f;
        float s = e0 + e1;
#pragma unroll
        for (int o = 16; o; o >>= 1) s += __shfl_xor_sync(0xffffffffu, s, o);
        float inv = 1.f / s;
        A[d][lane] = e0 * inv;
        if (lane + 32 < DD) A[d][lane + 32] = e1 * inv;
    }
    __syncthreads();

    if (tid < DD) {
        float s = 0.f;
        for (int d = 0; d < DD; d++) s += A[d][tid];
        cs[tid] = s;
    }
    __syncthreads();
    if (tid < 64)
        csbuf[((size_t)(b * NN_ + i) * NN_ + j) * 64 + tid] =
            (tid < DD) ? cs[tid] * (1.f / (float)DD) : 0.f;

    // tr(A^T A * M M^T), both symmetric: upper triangle only
    const float* mmt = MMT + (size_t)(b * NN_ + i) * DD * DD;
    float qa = 0.f;
    for (int t = tid; t < NPAIR; t += 256) {
        int pq = pairs[t];
        int p = pq >> 8, q = pq & 255;
        float s = 0.f;
        for (int d = 0; d < DD; d++) s += A[d][p] * A[d][q];
        float mv = mmt[p * DD + q];
        qa += s * mv * ((p == q) ? 1.f : 2.f);
    }
    int mrow = (b * NN_ + i) * DD;
    float s1l = (tid < DD) ? cs[tid] * Ms[mrow + tid] : 0.f;
    float mbl = (tid < DD) ? cs[tid] * Mb[mrow + tid] : 0.f;
    float S2q = blockReduceSum(qa, red);
    float S1  = blockReduceSum(s1l, red);
    float MBd = blockReduceSum(mbl, red);
    if (tid == 0) {
        part1[b * NE + e] = S1 + (float)DD * misc[0];
        part2[b * NE + e] = S2q + 2.f * MBd + (float)DD * misc[1];
    }
}

// ---------------- finalize edge BN scale/shift ----------------
__global__ void edge_finalize_kernel(const float* __restrict__ p1, const float* __restrict__ p2,
                                     const float* __restrict__ w, const float* __restrict__ bb,
                                     float* sc, float* sh)
{
    int e = blockIdx.x * blockDim.x + threadIdx.x;
    if (e >= NE) return;
    float s1 = 0.f, s2 = 0.f;
    for (int b = 0; b < BB; b++) { s1 += p1[b * NE + e]; s2 += p2[b * NE + e]; }
    const float cnt = (float)(BB * DD * CC);
    float mean = s1 / cnt;
    float var = s2 / cnt - mean * mean;
    float r = rsqrtf(var + BN_EPS);
    float scale = w[e] * r;
    sc[e] = scale;
    sh[e] = bb[e] - mean * scale;
}

// BN stats over (B,C) per feature f; data layout [B, F, 512]
__global__ void bnstat_bc_kernel(const float* __restrict__ data, int F,
                                 const float* __restrict__ w, const float* __restrict__ bb,
                                 float* sc, float* sh)
{
    int f = blockIdx.x;
    float s = 0.f, sq = 0.f;
    for (int b = 0; b < BB; b++) {
        const float* p = data + ((size_t)b * F + f) * CC;
        for (int c = threadIdx.x; c < CC; c += blockDim.x) { float v = p[c]; s += v; sq += v * v; }
    }
    __shared__ float red[32];
    s = blockReduceSum(s, red);
    sq = blockReduceSum(sq, red);
    if (threadIdx.x == 0) {
        float mean = s / 2048.f;
        float var = sq / 2048.f - mean * mean;
        float r = rsqrtf(var + BN_EPS);
        float scale = w[f] * r;
        sc[f] = scale;
        sh[f] = bb[f] - mean * scale;
    }
}

__global__ void fe_update_kernel(float* __restrict__ fe, const float* __restrict__ m,
                                 const float* __restrict__ sc, const float* __restrict__ sh)
{
    int idx = blockIdx.x * blockDim.x + threadIdx.x;
    if (idx >= BB * NE * CC) return;
    int e = (idx >> 9) % NE;
    fe[idx] += fmaxf(m[idx] * sc[e] + sh[e], 0.f);
}

__global__ void agg_kernel(const float* __restrict__ fe, const float* __restrict__ ui,
                           const float* __restrict__ uj, float* __restrict__ agg)
{
    int idx = blockIdx.x * blockDim.x + threadIdx.x;
    if (idx >= BB * NN_ * CC) return;
    int c = idx & 511;
    int i = (idx >> 9) % NN_;
    int b = idx / (NN_ * CC);
    const float* fer = fe + ((size_t)b * NE + i * NN_) * CC + c;
    float sw = 0.f, swu = 0.f;
    for (int j = 0; j < NN_; j++) {
        float f = fer[(size_t)j * CC];
        float s = 1.f / (1.f + __expf(-f));
        float wv = __expf(s);
        sw += wv;
        swu += wv * uj[(size_t)(b * NN_ + j) * VLD + c];
    }
    agg[idx] = ui[(size_t)(b * NN_ + i) * VLD + c] + swu / (sw * (float)NN_);
}

__global__ void fv_update_kernel(float* __restrict__ fv, const float* __restrict__ agg,
                                 const float* __restrict__ sc, const float* __restrict__ sh)
{
    int idx = blockIdx.x * blockDim.x + threadIdx.x;
    if (idx >= BB * NN_ * CC) return;
    int i = (idx >> 9) % NN_;
    fv[idx] += fmaxf(agg[idx] * sc[i] + sh[i], 0.f);
}

// ---------------- final SC cosine similarities ----------------
__global__ void sc_kernel(const float* __restrict__ fv, const float* __restrict__ mainsc,
                          const float* __restrict__ subsc, float* __restrict__ out)
{
    int o = blockIdx.x, b = blockIdx.y;
    int node;
    const float* anchor;
    if (o < NN_) { node = o; anchor = mainsc + (size_t)o * CC; }
    else { node = c_subidx[o - NN_]; anchor = subsc + (size_t)(o - NN_) * CC; }
    const float* fp = fv + ((size_t)b * NN_ + node) * CC;
    float dot = 0.f, nv = 0.f, na = 0.f;
    for (int c = threadIdx.x; c < CC; c += blockDim.x) {
        float f = fp[c], a = fmaxf(anchor[c], 0.f);
        dot += f * a; nv += f * f; na += a * a;
    }
    __shared__ float red[32];
    dot = blockReduceSum(dot, red);
    nv = blockReduceSum(nv, red);
    na = blockReduceSum(na, red);
    if (threadIdx.x == 0)
        out[b * 41 + o] = dot / (fmaxf(sqrtf(nv), 1e-12f) * fmaxf(sqrtf(na), 1e-12f));
}

// ==================================================================================
extern "C" void kernel_launch(void* const* d_in, const int* in_sizes, int n_in,
                              void* d_out, int out_size)
{
    const float* x       = (const float*)d_in[0];
    const float* nb_W    = (const float*)d_in[1];
    const float* nb_b    = (const float*)d_in[2];
    const float* nb_bnw  = (const float*)d_in[3];
    const float* nb_bnb  = (const float*)d_in[4];
    const float* fam_qW  = (const float*)d_in[5];
    const float* fam_qb  = (const float*)d_in[6];
    const float* fam_kW  = (const float*)d_in[7];
    const float* fam_kb  = (const float*)d_in[8];
    const float* fam_vW  = (const float*)d_in[9];
    const float* fam_vb  = (const float*)d_in[10];
    const float* arm_qW  = (const float*)d_in[11];
    const float* arm_qb  = (const float*)d_in[12];
    const float* arm_kW  = (const float*)d_in[13];
    const float* arm_kb  = (const float*)d_in[14];
    const float* arm_vW  = (const float*)d_in[15];
    const float* arm_vb  = (const float*)d_in[16];
    const float* ep_W    = (const float*)d_in[17];
    const float* ep_b    = (const float*)d_in[18];
    const float* gem_bnw = (const float*)d_in[19];
    const float* gem_bnb = (const float*)d_in[20];
    const float* gnn_uW  = (const float*)d_in[21];
    const float* gnn_vW  = (const float*)d_in[22];
    const float* gnn_aW  = (const float*)d_in[23];
    const float* gnn_bW  = (const float*)d_in[24];
    const float* gnn_eW  = (const float*)d_in[25];
    const float* gnn_bnvw = (const float*)d_in[26];
    const float* gnn_bnvb = (const float*)d_in[27];
    const float* gnn_bnew = (const float*)d_in[28];
    const float* gnn_bneb = (const float*)d_in[29];
    const float* main_sc = (const float*)d_in[30];
    const float* sub_sc  = (const float*)d_in[31];
    float* out = (float*)d_out;

    float* S = nullptr;
    cudaGetSymbolAddress((void**)&S, g_scratch);
    int* pairs = nullptr;
    cudaGetSymbolAddress((void**)&pairs, g_pairs);

    size_t off = 0;
    auto take = [&](size_t n) { float* p = S + off; off += (n + 3) & ~(size_t)3; return p; };
    float* tmp_   = take((size_t)NN_ * BD * CC);
    float* fu_    = take((size_t)BB * NN_ * DD * CC);
    float* feat_  = take((size_t)BB * ND * CC);
    float* VP_    = take((size_t)BB * ND * CC);
    float* q_     = take((size_t)BB * ND * C2);
    float* QK_    = take((size_t)BB * ND * CC);      // [MR, 512]: Q = cols 0..255, K = 256..511
    float* dots_  = take((size_t)BB * ND * ND);
    float* fe_    = take((size_t)BB * NE * CC);
    float* el_    = take((size_t)BB * NE * CC);
    float* attnp_ = take((size_t)BB * ND * 64);      // padded attention
    float* MMT_   = take((size_t)BB * NN_ * DD * DD);
    float* kb_    = take((size_t)BB * DD * C2);
    float* vbp_   = take((size_t)BB * 64 * CC);      // padded V
    float* fv_    = take((size_t)BB * NN_ * CC);
    float* W2_    = take((size_t)CC * CC);
    float* Wqk_   = take((size_t)CC * CC);           // [512,512]: rows 0..255 qW, 256..511 kW
    float* qkb_   = take(CC);
    float* Wcat_  = take((size_t)2 * 4 * CC * CC);   // per-layer [2048, 512]
    float* vcat_  = take((size_t)BB * NN_ * VLD);    // [108, 2048]: vi|vj|ui|uj
    float* csbuf_ = take((size_t)BB * NN_ * NN_ * 64);
    float* nmean_ = take(NN_ * CC);
    float* nrstd_ = take(NN_ * CC);
    float* Ms_    = take(MR);
    float* Mb_    = take(MR);
    float* part1_ = take(BB * NE);
    float* part2_ = take(BB * NE);
    float* esc_   = take(NE);
    float* esh_   = take(NE);
    float* agg_   = take((size_t)BB * NN_ * CC);
    float* bias2_ = take(CC);
    float* misc_  = take(2);
    float* emsc_  = take(NE);
    float* emsh_  = take(NE);
    float* nvsc_  = take(NN_);
    float* nvsh_  = take(NN_);

    const size_t WSZ = (size_t)CC * CC;

    auto f2_nt = [](const float* A, int lda, size_t sA, const float* Bm, int ldb, size_t sB,
                    float* Cc, int ldc, size_t sC, const float* bias, size_t sBias,
                    int M, int Nn, int K, int batch, float alpha) {
        dim3 g((Nn + 127) / 128, (M + 127) / 128, batch);
        gemm_f2<true><<<g, 256>>>(A, lda, sA, Bm, ldb, sB, Cc, ldc, sC, bias, sBias, M, Nn, K, alpha);
    };
    auto f2_nn = [](const float* A, int lda, size_t sA, const float* Bm, int ldb, size_t sB,
                    float* Cc, int ldc, size_t sC, const float* bias, size_t sBias,
                    int M, int Nn, int K, int batch, float alpha) {
        dim3 g((Nn + 127) / 128, (M + 127) / 128, batch);
        gemm_f2<false><<<g, 256>>>(A, lda, sA, Bm, ldb, sB, Cc, ldc, sC, bias, sBias, M, Nn, K, alpha);
    };
    auto small_nt = [](const float* A, int lda, size_t sA, const float* Bm, int ldb, size_t sB,
                       float* Cc, int ldc, size_t sC, const float* bias, size_t sBias,
                       int M, int Nn, int K, int batch, float alpha) {
        dim3 g((Nn + 31) / 32, (M + 31) / 32, batch);
        gemm_small<true, 0><<<g, 256>>>(A, lda, sA, Bm, ldb, sB, Cc, ldc, sC, bias, sBias,
                                        M, Nn, K, alpha, nullptr, nullptr);
    };
    auto small_nn = [](const float* A, int lda, size_t sA, const float* Bm, int ldb, size_t sB,
                       float* Cc, int ldc, size_t sC, const float* bias, size_t sBias,
                       int M, int Nn, int K, int batch, float alpha) {
        dim3 g((Nn + 31) / 32, (M + 31) / 32, batch);
        gemm_small<false, 0><<<g, 256>>>(A, lda, sA, Bm, ldb, sB, Cc, ldc, sC, bias, sBias,
                                         M, Nn, K, alpha, nullptr, nullptr);
    };

    pair_init_kernel<<<(NPAIR + 255) / 256, 256>>>(pairs);

    // ---- weight concats (D2D copies; graph-capturable) ----
    cudaMemcpyAsync(Wqk_, arm_qW, (size_t)C2 * CC * 4, cudaMemcpyDeviceToDevice);
    cudaMemcpyAsync(Wqk_ + (size_t)C2 * CC, arm_kW, (size_t)C2 * CC * 4, cudaMemcpyDeviceToDevice);
    cudaMemcpyAsync(qkb_, arm_qb, C2 * 4, cudaMemcpyDeviceToDevice);
    cudaMemcpyAsync(qkb_ + C2, arm_kb, C2 * 4, cudaMemcpyDeviceToDevice);
    for (int l = 0; l < 2; l++) {
        float* W = Wcat_ + (size_t)l * 4 * WSZ;
        cudaMemcpyAsync(W + 0 * WSZ, gnn_aW + (size_t)l * WSZ, WSZ * 4, cudaMemcpyDeviceToDevice);
        cudaMemcpyAsync(W + 1 * WSZ, gnn_bW + (size_t)l * WSZ, WSZ * 4, cudaMemcpyDeviceToDevice);
        cudaMemcpyAsync(W + 2 * WSZ, gnn_uW + (size_t)l * WSZ, WSZ * 4, cudaMemcpyDeviceToDevice);
        cudaMemcpyAsync(W + 3 * WSZ, gnn_vW + (size_t)l * WSZ, WSZ * 4, cudaMemcpyDeviceToDevice);
    }

    // ---- precompute W2 = ep_W @ arm_vW, bias2 = ep_W @ arm_vb, ep_b sums ----
    small_nn(ep_W, CC, 0, arm_vW, CC, 0, W2_, CC, 0, nullptr, 0, CC, CC, CC, 1, 1.f);
    misc_kernel<<<1, 512>>>(ep_W, arm_vb, ep_b, bias2_, misc_);

    // ---- node blocks ----
    f2_nt(x, CC, 0, nb_W, CC, WSZ, tmp_, CC, (size_t)BD * CC, nb_b, CC,
          BD, CC, CC, NN_, 1.f);
    bnstat_node_kernel<<<(NN_ * CC + 255) / 256, 256>>>(tmp_, nmean_, nrstd_);
    node_apply_fused<<<(BB * NN_ * CC + 255) / 256, 256>>>(tmp_, nmean_, nrstd_,
                                                           nb_bnw, nb_bnb, fu_, fv_);

    // ---- FAM cross attention ----
    small_nt(x, CC, 0, fam_kW, CC, 0, kb_, C2, 0, fam_kb, 0, BD, C2, CC, 1, 1.f);
    // V padded to [BB][64][512] (rows 49..63 zeroed)
    small_nt(x, CC, (size_t)DD * CC, fam_vW, CC, 0, vbp_, CC, (size_t)64 * CC, fam_vb, 0,
             DD, CC, CC, BB, 1.f);
    vbp_zero_kernel<<<(BB * 15 * CC + 255) / 256, 256>>>(vbp_);
    {   // q = fu @ fam_qW^T (gemm_fast, N=256)
        dim3 g((C2 + 63) / 64, (MR + 127) / 128, 1);
        gemm_fast<true, 0><<<g, 256>>>(fu_, 0, fam_qW, 0, q_, 0, fam_qb, 0,
                                       MR, C2, CC, 1.f, nullptr, nullptr, 0);
    }
    small_nt(q_, C2, (size_t)ND * C2, kb_, C2, (size_t)DD * C2, attnp_, 64, (size_t)ND * 64,
             nullptr, 0, ND, DD, C2, BB, SCALE);
    softmax49_kernel<<<(MR + 7) / 8, 256>>>(attnp_, MR);
    // feat = attn_p @ vb_p  (K=64 fast path)
    f2_nn(attnp_, 64, (size_t)ND * 64, vbp_, CC, (size_t)64 * CC, feat_, CC, (size_t)ND * CC,
          nullptr, 0, ND, CC, 64, BB, 1.f);

    // ---- ARM projections: QK fused, VP (V folded with ep_W) ----
    f2_nt(feat_, CC, 0, Wqk_, CC, 0, QK_, CC, 0, qkb_, 0, MR, CC, CC, 1, 1.f);
    f2_nt(feat_, CC, 0, W2_, CC, 0, VP_, CC, 0, bias2_, 0, MR, CC, CC, 1, 1.f);

    // ---- pairwise dots: Q @ K^T, Q/K are column halves of QK_ ----
    f2_nt(QK_, CC, (size_t)ND * CC, QK_ + C2, CC, (size_t)ND * CC, dots_, ND, (size_t)ND * ND,
          nullptr, 0, ND, ND, C2, BB, SCALE);

    // ---- per-(b,i): M M^T (upper), row sums, M@ep_b ----
    mmt_kernel<<<BB * NN_, 256>>>(VP_, pairs, MMT_);
    msmb_kernel<<<(MR + 7) / 8, 256>>>(VP_, ep_b, Ms_, Mb_);

    // ---- per-edge: softmax + BN-stat partials; export colsum/D (padded 64) ----
    {
        dim3 g(NE, BB);
        edge_kernel<<<g, 256>>>(dots_, MMT_, Ms_, Mb_, misc_, pairs, part1_, part2_, csbuf_);
    }
    edge_finalize_kernel<<<(NE + 255) / 256, 256>>>(part1_, part2_, gem_bnw, gem_bnb, esc_, esh_);
    // fe[b, i*27+j, :] = BN affine applied in epilogue: ((cs/D)@VP + ep_b)*esc + esh
    {
        dim3 g((CC + 31) / 32, (NN_ + 31) / 32, BB * NN_);
        gemm_small<false, 2><<<g, 256>>>(csbuf_, 64, (size_t)NN_ * 64, VP_, CC, (size_t)DD * CC,
                                         fe_, CC, (size_t)NN_ * CC, ep_b, 0,
                                         NN_, CC, DD, 1.f, esc_, esh_);
    }

    // ---- 2 GatedGNN layers ----
    for (int l = 0; l < 2; l++) {
        const float* eW = gnn_eW + (size_t)l * WSZ;
        const float* Wc = Wcat_ + (size_t)l * 4 * WSZ;
        float* vi_ = vcat_ + 0;
        float* vj_ = vcat_ + 512;
        float* ui_ = vcat_ + 1024;
        float* uj_ = vcat_ + 1536;
        // vcat = fv @ [aW;bW;uW;vW]^T  -> [108, 2048]
        small_nt(fv_, CC, 0, Wc, CC, 0, vcat_, VLD, 0, nullptr, 0,
                 BB * NN_, 4 * CC, CC, 1, 1.f);
        // el = fe @ eW^T + vi[b,i] + vj[b,j]
        {
            dim3 g((CC + 63) / 64, (BB * NE + 127) / 128, 1);
            gemm_fast<true, 1><<<g, 256>>>(fe_, 0, eW, 0, el_, 0, nullptr, 0,
                                           BB * NE, CC, CC, 1.f, vi_, vj_, VLD);
        }
        int tot = BB * NE * CC;
        bnstat_bc_kernel<<<NE, 256>>>(el_, NE, gnn_bnew + (size_t)l * NE, gnn_bneb + (size_t)l * NE,
                                      emsc_, emsh_);
        fe_update_kernel<<<(tot + 255) / 256, 256>>>(fe_, el_, emsc_, emsh_);
        agg_kernel<<<(BB * NN_ * CC + 255) / 256, 256>>>(fe_, ui_, uj_, agg_);
        bnstat_bc_kernel<<<NN_, 256>>>(agg_, NN_, gnn_bnvw + (size_t)l * NN_,
                                       gnn_bnvb + (size_t)l * NN_, nvsc_, nvsh_);
        fv_update_kernel<<<(BB * NN_ * CC + 255) / 256, 256>>>(fv_, agg_, nvsc_, nvsh_);
    }

    // ---- SC cosine outputs ----
    {
        dim3 g(41, BB);
        sc_kernel<<<g, 128>>>(fv_, main_sc, sub_sc, out);
    }
}